// round 1
// baseline (speedup 1.0000x reference)
#include <cuda_runtime.h>
#include <math.h>

// ---------------- problem constants ----------------
#define BB 2
#define SS 1024
#define UU 1024
#define HH 16
#define DD 64
#define NT 32000
#define MEMLEN 576
#define FFD 4096
#define KLEN 1600   // MEM + S
#define VOCAB 1024

// ---------------- scratch (device globals; no allocation allowed) ----------------
__device__ float g_x   [(size_t)BB*SS*UU];
__device__ float g_full[(size_t)BB*KLEN*UU];
__device__ float g_q   [(size_t)BB*SS*UU];
__device__ float g_kv  [(size_t)BB*KLEN*2*UU];
__device__ float g_rel [(size_t)KLEN*UU];
__device__ float g_r   [(size_t)KLEN*UU];
__device__ float g_ac  [(size_t)BB*HH*SS*KLEN];
__device__ float g_ar  [(size_t)BB*HH*SS*KLEN];
__device__ float g_ctx [(size_t)BB*SS*UU];
__device__ float g_tmp [(size_t)BB*SS*UU];
__device__ float g_h1  [(size_t)BB*SS*UU];
__device__ float g_ff  [(size_t)BB*SS*FFD];
__device__ float g_h2  [(size_t)BB*SS*UU];

// ---------------- reductions ----------------
__device__ __forceinline__ float block_reduce_sum(float v) {
    __shared__ float sm[8];
    __syncthreads();
    #pragma unroll
    for (int o = 16; o > 0; o >>= 1) v += __shfl_xor_sync(0xffffffffu, v, o);
    if ((threadIdx.x & 31) == 0) sm[threadIdx.x >> 5] = v;
    __syncthreads();
    if (threadIdx.x < 32) {
        float x = (threadIdx.x < 8) ? sm[threadIdx.x] : 0.f;
        #pragma unroll
        for (int o = 4; o > 0; o >>= 1) x += __shfl_xor_sync(0xffffffffu, x, o);
        if (threadIdx.x == 0) sm[0] = x;
    }
    __syncthreads();
    return sm[0];
}

__device__ __forceinline__ float block_reduce_max(float v) {
    __shared__ float sm[8];
    __syncthreads();
    #pragma unroll
    for (int o = 16; o > 0; o >>= 1) v = fmaxf(v, __shfl_xor_sync(0xffffffffu, v, o));
    if ((threadIdx.x & 31) == 0) sm[threadIdx.x >> 5] = v;
    __syncthreads();
    if (threadIdx.x < 32) {
        float x = (threadIdx.x < 8) ? sm[threadIdx.x] : -3.4e38f;
        #pragma unroll
        for (int o = 4; o > 0; o >>= 1) x = fmaxf(x, __shfl_xor_sync(0xffffffffu, x, o));
        if (threadIdx.x == 0) sm[0] = x;
    }
    __syncthreads();
    return sm[0];
}

// ---------------- generic SGEMM ----------------
// C[m,n] = sum_k (A[m,k] + aadd[k]) * B(k,n)  (+ bias[n]) (relu)
// TRANSB=false: B element (k,n) at B[k*ldb + n]
// TRANSB=true : B element (k,n) at B[n*ldb + k]
// batch: z = blockIdx.z; z1 = z/Z2, z2 = z%Z2; ptr += z1*s?1 + z2*s?2
template <bool TRANSB, bool RELU>
__global__ __launch_bounds__(256)
void sgemm(const float* __restrict__ A, const float* __restrict__ B,
           float* __restrict__ C, const float* __restrict__ bias,
           const float* __restrict__ aadd,
           int M, int N, int K, int lda, int ldb, int ldc,
           int Z2,
           long long sA1, long long sA2, long long sB1, long long sB2,
           long long sC1, long long sC2, long long sAdd2)
{
    const int BM = 128, BN = 64, BK = 16, TM = 8, TN = 4;
    __shared__ float As[BK][BM + 4];
    __shared__ float Bs[BK][BN];

    int tid = threadIdx.x;
    int tx = tid & 15, ty = tid >> 4;
    int m0 = blockIdx.y * BM, n0 = blockIdx.x * BN;
    int z = blockIdx.z;
    int z1 = z / Z2, z2 = z - z1 * Z2;
    A += z1 * sA1 + z2 * sA2;
    B += z1 * sB1 + z2 * sB2;
    C += z1 * sC1 + z2 * sC2;
    if (aadd) aadd += z2 * sAdd2;

    float acc[TM][TN];
    #pragma unroll
    for (int i = 0; i < TM; i++)
        #pragma unroll
        for (int j = 0; j < TN; j++) acc[i][j] = 0.f;

    for (int k0 = 0; k0 < K; k0 += BK) {
        // A tile: 128x16 = 2048 elems, 8 per thread
        #pragma unroll
        for (int i = 0; i < 8; i++) {
            int e = tid + i * 256;
            int r = e >> 4, c = e & 15;
            int gm = m0 + r, gk = k0 + c;
            float v = 0.f;
            if (gm < M && gk < K) {
                v = A[(long long)gm * lda + gk];
                if (aadd) v += aadd[gk];
            }
            As[c][r] = v;
        }
        // B tile: 16x64 = 1024 elems, 4 per thread
        #pragma unroll
        for (int i = 0; i < 4; i++) {
            int e = tid + i * 256;
            if (!TRANSB) {
                int r = e >> 6, c = e & 63;
                int gk = k0 + r, gn = n0 + c;
                Bs[r][c] = (gk < K && gn < N) ? B[(long long)gk * ldb + gn] : 0.f;
            } else {
                int r = e >> 4, c = e & 15;
                int gn = n0 + r, gk = k0 + c;
                Bs[c][r] = (gn < N && gk < K) ? B[(long long)gn * ldb + gk] : 0.f;
            }
        }
        __syncthreads();
        #pragma unroll
        for (int kk = 0; kk < BK; kk++) {
            float a[TM], b[TN];
            #pragma unroll
            for (int i = 0; i < TM; i++) a[i] = As[kk][ty * TM + i];
            #pragma unroll
            for (int j = 0; j < TN; j++) b[j] = Bs[kk][tx * TN + j];
            #pragma unroll
            for (int i = 0; i < TM; i++)
                #pragma unroll
                for (int j = 0; j < TN; j++) acc[i][j] = fmaf(a[i], b[j], acc[i][j]);
        }
        __syncthreads();
    }
    #pragma unroll
    for (int i = 0; i < TM; i++) {
        int gm = m0 + ty * TM + i;
        if (gm >= M) continue;
        #pragma unroll
        for (int j = 0; j < TN; j++) {
            int gn = n0 + tx * TN + j;
            if (gn >= N) continue;
            float v = acc[i][j];
            if (bias) v += bias[gn];
            if (RELU) v = fmaxf(v, 0.f);
            C[(long long)gm * ldc + gn] = v;
        }
    }
}

// ---------------- small kernels ----------------
__global__ void build_full(const int* __restrict__ tokens,
                           const float* __restrict__ memory,
                           const float* __restrict__ embed,
                           float* __restrict__ x, float* __restrict__ full)
{
    long long idx = (long long)blockIdx.x * 256 + threadIdx.x;
    const long long tot = (long long)BB * KLEN * UU;
    if (idx >= tot) return;
    int u = (int)(idx % UU);
    long long t = idx / UU;
    int j = (int)(t % KLEN);
    int b = (int)(t / KLEN);
    float v;
    if (j < MEMLEN) {
        v = memory[((long long)b * MEMLEN + j) * UU + u];
    } else {
        int s = j - MEMLEN;
        int tok = tokens[b * SS + s];
        v = embed[(long long)tok * UU + u] * 32.0f;  // sqrt(1024)
        x[((long long)b * SS + s) * UU + u] = v;
    }
    full[idx] = v;
}

__global__ void pos_embed(float* __restrict__ rel)
{
    long long idx = (long long)blockIdx.x * 256 + threadIdx.x;
    if (idx >= (long long)KLEN * UU) return;
    int u = (int)(idx % UU);
    int jj = (int)(idx / UU);
    double pos = (double)(KLEN - 1 - jj);
    int i2 = (u < UU / 2) ? u : (u - UU / 2);
    double expo = ((double)(2 * i2)) / (double)UU;
    double invf = exp(-expo * log(10000.0));
    double ang = pos * invf;
    rel[idx] = (u < UU / 2) ? (float)sin(ang) : (float)cos(ang);
}

// mask + rel-shift + softmax, in place on ac. P rows zeroed past the mask.
__global__ __launch_bounds__(256)
void attn_softmax(float* __restrict__ ac, const float* __restrict__ ar)
{
    int i = blockIdx.x;
    long long z = blockIdx.y;
    float* row = ac + (z * SS + i) * (long long)KLEN;
    const float* arow = ar + (z * SS + i) * (long long)KLEN;
    int lim = i + MEMLEN;         // inclusive
    int shift = SS - 1 - i;       // rel_shift: att[i,j] = ac[i,j] + ar[i, j+shift]
    int tid = threadIdx.x;

    float lmax = -3.4e38f;
    for (int j = tid; j <= lim; j += 256) {
        float v = (row[j] + arow[j + shift]) * 0.125f;  // 1/sqrt(64)
        row[j] = v;
        lmax = fmaxf(lmax, v);
    }
    float m = block_reduce_max(lmax);
    float lsum = 0.f;
    for (int j = tid; j <= lim; j += 256) {
        float e = expf(row[j] - m);
        row[j] = e;
        lsum += e;
    }
    float s = block_reduce_sum(lsum);
    float inv = 1.f / s;
    for (int j = tid; j <= lim; j += 256) row[j] *= inv;
    for (int j = lim + 1 + tid; j < KLEN; j += 256) row[j] = 0.f;
}

__global__ __launch_bounds__(256)
void add_ln(const float* __restrict__ a, const float* __restrict__ b,
            const float* __restrict__ g, const float* __restrict__ beta,
            float* __restrict__ out)
{
    long long row = blockIdx.x;
    const float* pa = a + row * UU;
    const float* pb = b + row * UU;
    float* po = out + row * UU;
    int tid = threadIdx.x;
    float vals[4];
    float s = 0.f, ss = 0.f;
    #pragma unroll
    for (int t = 0; t < 4; t++) {
        int idx = tid * 4 + t;
        float v = pa[idx] + pb[idx];
        vals[t] = v;
        s += v;
        ss += v * v;
    }
    s = block_reduce_sum(s);
    ss = block_reduce_sum(ss);
    float mean = s * (1.f / UU);
    float var = fmaxf(ss * (1.f / UU) - mean * mean, 0.f);
    float rstd = rsqrtf(var + 1e-5f);
    #pragma unroll
    for (int t = 0; t < 4; t++) {
        int idx = tid * 4 + t;
        po[idx] = (vals[t] - mean) * rstd * g[idx] + beta[idx];
    }
}

__global__ __launch_bounds__(256)
void softmax_rows(float* __restrict__ x, int N)
{
    long long row = blockIdx.x;
    float* p = x + row * (long long)N;
    int tid = threadIdx.x;
    float lmax = -3.4e38f;
    for (int j = tid; j < N; j += 256) lmax = fmaxf(lmax, p[j]);
    float m = block_reduce_max(lmax);
    float lsum = 0.f;
    for (int j = tid; j < N; j += 256) lsum += expf(p[j] - m);
    float s = block_reduce_sum(lsum);
    float inv = 1.f / s;
    for (int j = tid; j < N; j += 256) p[j] = expf(p[j] - m) * inv;
}

// ---------------- host ----------------
static void launch_gemm(bool transb, bool relu,
                        const float* A, const float* Bm, float* Cm,
                        const float* bias, const float* aadd,
                        int M, int N, int K, int lda, int ldb, int ldc,
                        int Z, int Z2,
                        long long sA1, long long sA2, long long sB1, long long sB2,
                        long long sC1, long long sC2, long long sAdd2)
{
    dim3 grid((N + 63) / 64, (M + 127) / 128, Z);
    dim3 blk(256);
    if (!transb && !relu)
        sgemm<false, false><<<grid, blk>>>(A, Bm, Cm, bias, aadd, M, N, K, lda, ldb, ldc,
                                           Z2, sA1, sA2, sB1, sB2, sC1, sC2, sAdd2);
    else if (!transb && relu)
        sgemm<false, true><<<grid, blk>>>(A, Bm, Cm, bias, aadd, M, N, K, lda, ldb, ldc,
                                          Z2, sA1, sA2, sB1, sB2, sC1, sC2, sAdd2);
    else
        sgemm<true, false><<<grid, blk>>>(A, Bm, Cm, bias, aadd, M, N, K, lda, ldb, ldc,
                                          Z2, sA1, sA2, sB1, sB2, sC1, sC2, sAdd2);
}

extern "C" void kernel_launch(void* const* d_in, const int* in_sizes, int n_in,
                              void* d_out, int out_size)
{
    const int*   tokens  = (const int*)  d_in[0];
    const float* memory  = (const float*)d_in[1];
    const float* embed   = (const float*)d_in[2];
    const float* Wq      = (const float*)d_in[3];
    const float* Wkv     = (const float*)d_in[4];
    const float* Wr      = (const float*)d_in[5];
    const float* Wo      = (const float*)d_in[6];
    const float* bq      = (const float*)d_in[7];
    const float* bkv     = (const float*)d_in[8];
    const float* br      = (const float*)d_in[9];
    const float* bo      = (const float*)d_in[10];
    const float* bias_c  = (const float*)d_in[11];
    const float* bias_r  = (const float*)d_in[12];
    const float* ln1_g   = (const float*)d_in[13];
    const float* ln1_b   = (const float*)d_in[14];
    const float* W1      = (const float*)d_in[15];
    const float* b1      = (const float*)d_in[16];
    const float* W2      = (const float*)d_in[17];
    const float* b2      = (const float*)d_in[18];
    const float* ln2_g   = (const float*)d_in[19];
    const float* ln2_b   = (const float*)d_in[20];
    const float* Wout    = (const float*)d_in[21];
    const float* bout    = (const float*)d_in[22];
    float* out = (float*)d_out;

    float *x, *full, *q, *kv, *rel, *r, *ac, *ar, *ctx, *tmp, *h1, *ff, *h2;
    cudaGetSymbolAddress((void**)&x,    g_x);
    cudaGetSymbolAddress((void**)&full, g_full);
    cudaGetSymbolAddress((void**)&q,    g_q);
    cudaGetSymbolAddress((void**)&kv,   g_kv);
    cudaGetSymbolAddress((void**)&rel,  g_rel);
    cudaGetSymbolAddress((void**)&r,    g_r);
    cudaGetSymbolAddress((void**)&ac,   g_ac);
    cudaGetSymbolAddress((void**)&ar,   g_ar);
    cudaGetSymbolAddress((void**)&ctx,  g_ctx);
    cudaGetSymbolAddress((void**)&tmp,  g_tmp);
    cudaGetSymbolAddress((void**)&h1,   g_h1);
    cudaGetSymbolAddress((void**)&ff,   g_ff);
    cudaGetSymbolAddress((void**)&h2,   g_h2);

    const int M_TOK = BB * SS;      // 2048
    const int M_FULL = BB * KLEN;   // 3200

    // 1) embedding + concat(memory, x)
    {
        long long tot = (long long)BB * KLEN * UU;
        build_full<<<(unsigned)((tot + 255) / 256), 256>>>(tokens, memory, embed, x, full);
    }
    // 2) sinusoidal relative positions
    {
        long long tot = (long long)KLEN * UU;
        pos_embed<<<(unsigned)((tot + 255) / 256), 256>>>(rel);
    }
    // 3) q = x@Wq + bq
    launch_gemm(false, false, x, Wq, q, bq, nullptr,
                M_TOK, UU, UU, UU, UU, UU, 1, 1, 0,0,0,0,0,0,0);
    // 4) kv = full@Wkv + bkv
    launch_gemm(false, false, full, Wkv, kv, bkv, nullptr,
                M_FULL, 2*UU, UU, UU, 2*UU, 2*UU, 1, 1, 0,0,0,0,0,0,0);
    // 5) r = rel@Wr + br
    launch_gemm(false, false, rel, Wr, r, br, nullptr,
                KLEN, UU, UU, UU, UU, UU, 1, 1, 0,0,0,0,0,0,0);
    // 6) content scores: ac[b,h,i,j] = (q+u)[b,i,h,:] . k[b,j,h,:]
    launch_gemm(true, false, q, kv, ac, nullptr, bias_c,
                SS, KLEN, DD, UU, 2*UU, KLEN,
                BB*HH, HH,
                (long long)SS*UU, 64,                 // A: b,h
                (long long)KLEN*2*UU, 64,             // B(k): b,h
                (long long)HH*SS*KLEN, (long long)SS*KLEN,  // C: b,h
                64);
    // 7) position scores (unshifted): ar[b,h,i,jj] = (q+v)[b,i,h,:] . r[jj,h,:]
    launch_gemm(true, false, q, r, ar, nullptr, bias_r,
                SS, KLEN, DD, UU, UU, KLEN,
                BB*HH, HH,
                (long long)SS*UU, 64,
                0, 64,                                 // r shared over batch
                (long long)HH*SS*KLEN, (long long)SS*KLEN,
                64);
    // 8) fused rel-shift + mask + softmax (in place on ac)
    {
        dim3 grid(SS, BB * HH);
        attn_softmax<<<grid, 256>>>(ac, ar);
    }
    // 9) ctx[b,i,h,:] = sum_j P[b,h,i,j] * v[b,j,h,:]
    launch_gemm(false, false, ac, kv + UU, ctx, nullptr, nullptr,
                SS, DD, KLEN, KLEN, 2*UU, UU,
                BB*HH, HH,
                (long long)HH*SS*KLEN, (long long)SS*KLEN,
                (long long)KLEN*2*UU, 64,
                (long long)SS*UU, 64,
                0);
    // 10) attention output projection
    launch_gemm(false, false, ctx, Wo, tmp, bo, nullptr,
                M_TOK, UU, UU, UU, UU, UU, 1, 1, 0,0,0,0,0,0,0);
    // 11) h1 = LN(x + attn_out)
    add_ln<<<M_TOK, 256>>>(x, tmp, ln1_g, ln1_b, h1);
    // 12) ff = relu(h1@W1 + b1)
    launch_gemm(false, true, h1, W1, ff, b1, nullptr,
                M_TOK, FFD, UU, UU, FFD, FFD, 1, 1, 0,0,0,0,0,0,0);
    // 13) ff2 = ff@W2 + b2
    launch_gemm(false, false, ff, W2, tmp, b2, nullptr,
                M_TOK, UU, FFD, FFD, UU, UU, 1, 1, 0,0,0,0,0,0,0);
    // 14) h2 = LN(h1 + ff2)
    add_ln<<<M_TOK, 256>>>(h1, tmp, ln2_g, ln2_b, h2);
    // 15) logits = h2@Wout + bout -> d_out
    launch_gemm(false, false, h2, Wout, out, bout, nullptr,
                M_TOK, NT, UU, UU, NT, NT, 1, 1, 0,0,0,0,0,0,0);
    // 16) softmax over vocab, in place
    softmax_rows<<<M_TOK, 256>>>(out, NT);
}

// round 2
// speedup vs baseline: 1.7217x; 1.7217x over previous
#include <cuda_runtime.h>
#include <math.h>

// ---------------- problem constants ----------------
#define BB 2
#define SS 1024
#define UU 1024
#define HH 16
#define DD 64
#define NT 32000
#define MEMLEN 576
#define FFD 4096
#define KLEN 1600   // MEM + S
#define VOCAB 1024

// ---------------- scratch (device globals; no allocation allowed) ----------------
__device__ float g_x   [(size_t)BB*SS*UU];
__device__ float g_full[(size_t)BB*KLEN*UU];
__device__ float g_q   [(size_t)BB*SS*UU];
__device__ float g_kv  [(size_t)BB*KLEN*2*UU];
__device__ float g_rel [(size_t)KLEN*UU];
__device__ float g_r   [(size_t)KLEN*UU];
__device__ float g_ac  [(size_t)BB*HH*SS*KLEN];
__device__ float g_ar  [(size_t)BB*HH*SS*KLEN];
__device__ float g_ctx [(size_t)BB*SS*UU];
__device__ float g_tmp [(size_t)BB*SS*UU];
__device__ float g_h1  [(size_t)BB*SS*UU];
__device__ float g_ff  [(size_t)BB*SS*FFD];
__device__ float g_h2  [(size_t)BB*SS*UU];

// ---------------- reductions ----------------
__device__ __forceinline__ float block_reduce_sum(float v) {
    __shared__ float sm[8];
    __syncthreads();
    #pragma unroll
    for (int o = 16; o > 0; o >>= 1) v += __shfl_xor_sync(0xffffffffu, v, o);
    if ((threadIdx.x & 31) == 0) sm[threadIdx.x >> 5] = v;
    __syncthreads();
    if (threadIdx.x < 32) {
        float x = (threadIdx.x < (blockDim.x >> 5)) ? sm[threadIdx.x] : 0.f;
        #pragma unroll
        for (int o = 8; o > 0; o >>= 1) x += __shfl_xor_sync(0xffffffffu, x, o);
        if (threadIdx.x == 0) sm[0] = x;
    }
    __syncthreads();
    return sm[0];
}

__device__ __forceinline__ float block_reduce_max(float v) {
    __shared__ float sm[8];
    __syncthreads();
    #pragma unroll
    for (int o = 16; o > 0; o >>= 1) v = fmaxf(v, __shfl_xor_sync(0xffffffffu, v, o));
    if ((threadIdx.x & 31) == 0) sm[threadIdx.x >> 5] = v;
    __syncthreads();
    if (threadIdx.x < 32) {
        float x = (threadIdx.x < (blockDim.x >> 5)) ? sm[threadIdx.x] : -3.4e38f;
        #pragma unroll
        for (int o = 8; o > 0; o >>= 1) x = fmaxf(x, __shfl_xor_sync(0xffffffffu, x, o));
        if (threadIdx.x == 0) sm[0] = x;
    }
    __syncthreads();
    return sm[0];
}

// ---------------- fast SGEMM: 128xBN tile, 8x(BN/16) per thread ----------------
// C[m,n] = sum_k (A[m,k] + aadd[k]) * B(k,n)  (+ bias[n]) (relu)
// Requirements honored by all call sites: K % 16 == 0, N % 4 == 0,
// lda/ldb/ldc % 4 == 0, all base offsets % 4 == 0.
template <int BN, bool TRANSB, bool RELU>
__global__ __launch_bounds__(256, 2)
void sgemm2(const float* __restrict__ A, const float* __restrict__ B,
            float* __restrict__ C, const float* __restrict__ bias,
            const float* __restrict__ aadd,
            int M, int N, int K, int lda, int ldb, int ldc,
            int Z2,
            long long sA1, long long sA2, long long sB1, long long sB2,
            long long sC1, long long sC2, long long sAdd2)
{
    constexpr int BM = 128, BK = 16;
    constexpr int TM = 8, TN = BN / 16;
    constexpr int A4 = (BM * BK) / 4 / 256;     // float4s per thread for A tile (=2)
    constexpr int B4 = (BN * BK) / 4 / 256;     // 2 for BN=128, 1 for BN=64

    __shared__ float As[2][BK][BM + 4];
    __shared__ float Bs[2][BK][BN + 4];

    const int tid = threadIdx.x;
    const int tx = tid & 15, ty = tid >> 4;
    const int m0 = blockIdx.y * BM, n0 = blockIdx.x * BN;
    const int z  = blockIdx.z;
    const int z1 = z / Z2, z2 = z - z1 * Z2;
    A += z1 * sA1 + z2 * sA2;
    B += z1 * sB1 + z2 * sB2;
    C += z1 * sC1 + z2 * sC2;
    if (aadd) aadd += z2 * sAdd2;

    float acc[TM][TN];
    #pragma unroll
    for (int i = 0; i < TM; i++)
        #pragma unroll
        for (int j = 0; j < TN; j++) acc[i][j] = 0.f;

    float4 ra[A4], rb[B4];

    const int nk = K / BK;

    // ---- prologue: load tile 0 ----
    #pragma unroll
    for (int i = 0; i < A4; i++) {
        int e = tid + i * 256;
        int m = e >> 2, kq = e & 3;
        int gm = min(m0 + m, M - 1);
        float4 v = *(const float4*)(A + (long long)gm * lda + kq * 4);
        if (aadd) {
            float4 ad = *(const float4*)(aadd + kq * 4);
            v.x += ad.x; v.y += ad.y; v.z += ad.z; v.w += ad.w;
        }
        ra[i] = v;
    }
    #pragma unroll
    for (int i = 0; i < B4; i++) {
        int e = tid + i * 256;
        if (!TRANSB) {
            int kk = e / (BN / 4), nq = e % (BN / 4);
            int gn = min(n0 + nq * 4, N - 4);
            rb[i] = *(const float4*)(B + (long long)kk * ldb + gn);
        } else {
            int n = e >> 2, kq = e & 3;
            int gn = min(n0 + n, N - 1);
            rb[i] = *(const float4*)(B + (long long)gn * ldb + kq * 4);
        }
    }
    #pragma unroll
    for (int i = 0; i < A4; i++) {
        int e = tid + i * 256;
        int m = e >> 2, kq = e & 3;
        As[0][kq * 4 + 0][m] = ra[i].x;
        As[0][kq * 4 + 1][m] = ra[i].y;
        As[0][kq * 4 + 2][m] = ra[i].z;
        As[0][kq * 4 + 3][m] = ra[i].w;
    }
    #pragma unroll
    for (int i = 0; i < B4; i++) {
        int e = tid + i * 256;
        if (!TRANSB) {
            int kk = e / (BN / 4), nq = e % (BN / 4);
            *(float4*)&Bs[0][kk][nq * 4] = rb[i];
        } else {
            int n = e >> 2, kq = e & 3;
            Bs[0][kq * 4 + 0][n] = rb[i].x;
            Bs[0][kq * 4 + 1][n] = rb[i].y;
            Bs[0][kq * 4 + 2][n] = rb[i].z;
            Bs[0][kq * 4 + 3][n] = rb[i].w;
        }
    }
    __syncthreads();

    int buf = 0;
    for (int t = 0; t < nk; t++) {
        // prefetch next tile into registers (overlaps with compute)
        if (t + 1 < nk) {
            const int k0 = (t + 1) * BK;
            #pragma unroll
            for (int i = 0; i < A4; i++) {
                int e = tid + i * 256;
                int m = e >> 2, kq = e & 3;
                int gm = min(m0 + m, M - 1);
                float4 v = *(const float4*)(A + (long long)gm * lda + k0 + kq * 4);
                if (aadd) {
                    float4 ad = *(const float4*)(aadd + k0 + kq * 4);
                    v.x += ad.x; v.y += ad.y; v.z += ad.z; v.w += ad.w;
                }
                ra[i] = v;
            }
            #pragma unroll
            for (int i = 0; i < B4; i++) {
                int e = tid + i * 256;
                if (!TRANSB) {
                    int kk = e / (BN / 4), nq = e % (BN / 4);
                    int gn = min(n0 + nq * 4, N - 4);
                    rb[i] = *(const float4*)(B + (long long)(k0 + kk) * ldb + gn);
                } else {
                    int n = e >> 2, kq = e & 3;
                    int gn = min(n0 + n, N - 1);
                    rb[i] = *(const float4*)(B + (long long)gn * ldb + k0 + kq * 4);
                }
            }
        }

        // compute on current buffer
        #pragma unroll
        for (int kk = 0; kk < BK; kk++) {
            float a[TM], b[TN];
            *(float4*)&a[0] = *(const float4*)&As[buf][kk][ty * TM];
            *(float4*)&a[4] = *(const float4*)&As[buf][kk][ty * TM + 4];
            *(float4*)&b[0] = *(const float4*)&Bs[buf][kk][tx * TN];
            if (TN == 8)
                *(float4*)&b[4] = *(const float4*)&Bs[buf][kk][tx * TN + 4];
            #pragma unroll
            for (int i = 0; i < TM; i++)
                #pragma unroll
                for (int j = 0; j < TN; j++)
                    acc[i][j] = fmaf(a[i], b[j], acc[i][j]);
        }

        // store prefetched tile into the other buffer
        if (t + 1 < nk) {
            int nb = buf ^ 1;
            #pragma unroll
            for (int i = 0; i < A4; i++) {
                int e = tid + i * 256;
                int m = e >> 2, kq = e & 3;
                As[nb][kq * 4 + 0][m] = ra[i].x;
                As[nb][kq * 4 + 1][m] = ra[i].y;
                As[nb][kq * 4 + 2][m] = ra[i].z;
                As[nb][kq * 4 + 3][m] = ra[i].w;
            }
            #pragma unroll
            for (int i = 0; i < B4; i++) {
                int e = tid + i * 256;
                if (!TRANSB) {
                    int kk = e / (BN / 4), nq = e % (BN / 4);
                    *(float4*)&Bs[nb][kk][nq * 4] = rb[i];
                } else {
                    int n = e >> 2, kq = e & 3;
                    Bs[nb][kq * 4 + 0][n] = rb[i].x;
                    Bs[nb][kq * 4 + 1][n] = rb[i].y;
                    Bs[nb][kq * 4 + 2][n] = rb[i].z;
                    Bs[nb][kq * 4 + 3][n] = rb[i].w;
                }
            }
        }
        __syncthreads();
        buf ^= 1;
    }

    // ---- epilogue ----
    #pragma unroll
    for (int i = 0; i < TM; i++) {
        int gm = m0 + ty * TM + i;
        if (gm >= M) continue;
        #pragma unroll
        for (int j4 = 0; j4 < TN / 4; j4++) {
            int gn = n0 + tx * TN + j4 * 4;
            if (gn >= N) continue;
            float4 v;
            v.x = acc[i][j4 * 4 + 0];
            v.y = acc[i][j4 * 4 + 1];
            v.z = acc[i][j4 * 4 + 2];
            v.w = acc[i][j4 * 4 + 3];
            if (bias) {
                float4 bb = *(const float4*)(bias + gn);
                v.x += bb.x; v.y += bb.y; v.z += bb.z; v.w += bb.w;
            }
            if (RELU) {
                v.x = fmaxf(v.x, 0.f); v.y = fmaxf(v.y, 0.f);
                v.z = fmaxf(v.z, 0.f); v.w = fmaxf(v.w, 0.f);
            }
            *(float4*)(C + (long long)gm * ldc + gn) = v;
        }
    }
}

// ---------------- small kernels ----------------
__global__ void build_full(const int* __restrict__ tokens,
                           const float* __restrict__ memory,
                           const float* __restrict__ embed,
                           float* __restrict__ x, float* __restrict__ full)
{
    long long idx = (long long)blockIdx.x * 256 + threadIdx.x;
    const long long tot = (long long)BB * KLEN * UU;
    if (idx >= tot) return;
    int u = (int)(idx % UU);
    long long t = idx / UU;
    int j = (int)(t % KLEN);
    int b = (int)(t / KLEN);
    float v;
    if (j < MEMLEN) {
        v = memory[((long long)b * MEMLEN + j) * UU + u];
    } else {
        int s = j - MEMLEN;
        int tok = tokens[b * SS + s];
        v = embed[(long long)tok * UU + u] * 32.0f;  // sqrt(1024)
        x[((long long)b * SS + s) * UU + u] = v;
    }
    full[idx] = v;
}

__global__ void pos_embed(float* __restrict__ rel)
{
    long long idx = (long long)blockIdx.x * 256 + threadIdx.x;
    if (idx >= (long long)KLEN * UU) return;
    int u = (int)(idx % UU);
    int jj = (int)(idx / UU);
    float pos = (float)(KLEN - 1 - jj);
    int i2 = (u < UU / 2) ? u : (u - UU / 2);
    float expo = ((float)(2 * i2)) / (float)UU;
    float invf = expf(-expo * 9.210340371976184f);  // ln(10000)
    float ang = pos * invf;
    rel[idx] = (u < UU / 2) ? sinf(ang) : cosf(ang);
}

// mask + rel-shift + softmax, in place on ac. P rows zeroed past the mask.
__global__ __launch_bounds__(256)
void attn_softmax(float* __restrict__ ac, const float* __restrict__ ar)
{
    int i = blockIdx.x;
    long long z = blockIdx.y;
    float* row = ac + (z * SS + i) * (long long)KLEN;
    const float* arow = ar + (z * SS + i) * (long long)KLEN;
    int lim = i + MEMLEN;         // inclusive
    int shift = SS - 1 - i;       // rel_shift: att[i,j] = ac[i,j] + ar[i, j+shift]
    int tid = threadIdx.x;

    float lmax = -3.4e38f;
    for (int j = tid; j <= lim; j += 256) {
        float v = (row[j] + arow[j + shift]) * 0.125f;  // 1/sqrt(64)
        row[j] = v;
        lmax = fmaxf(lmax, v);
    }
    float m = block_reduce_max(lmax);
    float lsum = 0.f;
    for (int j = tid; j <= lim; j += 256) {
        float e = expf(row[j] - m);
        row[j] = e;
        lsum += e;
    }
    float s = block_reduce_sum(lsum);
    float inv = 1.f / s;
    for (int j = tid; j <= lim; j += 256) row[j] *= inv;
    for (int j = lim + 1 + tid; j < KLEN; j += 256) row[j] = 0.f;
}

__global__ __launch_bounds__(256)
void add_ln(const float* __restrict__ a, const float* __restrict__ b,
            const float* __restrict__ g, const float* __restrict__ beta,
            float* __restrict__ out)
{
    long long row = blockIdx.x;
    const float* pa = a + row * UU;
    const float* pb = b + row * UU;
    float* po = out + row * UU;
    int tid = threadIdx.x;
    float vals[4];
    float s = 0.f, ss = 0.f;
    #pragma unroll
    for (int t = 0; t < 4; t++) {
        int idx = tid * 4 + t;
        float v = pa[idx] + pb[idx];
        vals[t] = v;
        s += v;
        ss += v * v;
    }
    s = block_reduce_sum(s);
    ss = block_reduce_sum(ss);
    float mean = s * (1.f / UU);
    float var = fmaxf(ss * (1.f / UU) - mean * mean, 0.f);
    float rstd = rsqrtf(var + 1e-5f);
    #pragma unroll
    for (int t = 0; t < 4; t++) {
        int idx = tid * 4 + t;
        po[idx] = (vals[t] - mean) * rstd * g[idx] + beta[idx];
    }
}

__global__ __launch_bounds__(512)
void softmax_rows(float* __restrict__ x, int N)
{
    long long row = blockIdx.x;
    float* p = x + row * (long long)N;
    int tid = threadIdx.x;
    float lmax = -3.4e38f;
    for (int j = tid; j < N; j += 512) lmax = fmaxf(lmax, p[j]);
    float m = block_reduce_max(lmax);
    float lsum = 0.f;
    for (int j = tid; j < N; j += 512) {
        float e = expf(p[j] - m);
        p[j] = e;
        lsum += e;
    }
    float s = block_reduce_sum(lsum);
    float inv = 1.f / s;
    for (int j = tid; j < N; j += 512) p[j] *= inv;
}

// ---------------- host ----------------
static void launch_gemm(bool transb, bool relu,
                        const float* A, const float* Bm, float* Cm,
                        const float* bias, const float* aadd,
                        int M, int N, int K, int lda, int ldb, int ldc,
                        int Z, int Z2,
                        long long sA1, long long sA2, long long sB1, long long sB2,
                        long long sC1, long long sC2, long long sAdd2)
{
    dim3 blk(256);
    if (N == 64) {
        dim3 grid(1, (M + 127) / 128, Z);
        sgemm2<64, false, false><<<grid, blk>>>(A, Bm, Cm, bias, aadd, M, N, K,
                                                lda, ldb, ldc, Z2,
                                                sA1, sA2, sB1, sB2, sC1, sC2, sAdd2);
        return;
    }
    dim3 grid((N + 127) / 128, (M + 127) / 128, Z);
    if (!transb && !relu)
        sgemm2<128, false, false><<<grid, blk>>>(A, Bm, Cm, bias, aadd, M, N, K,
                                                 lda, ldb, ldc, Z2,
                                                 sA1, sA2, sB1, sB2, sC1, sC2, sAdd2);
    else if (!transb && relu)
        sgemm2<128, false, true><<<grid, blk>>>(A, Bm, Cm, bias, aadd, M, N, K,
                                                lda, ldb, ldc, Z2,
                                                sA1, sA2, sB1, sB2, sC1, sC2, sAdd2);
    else
        sgemm2<128, true, false><<<grid, blk>>>(A, Bm, Cm, bias, aadd, M, N, K,
                                                lda, ldb, ldc, Z2,
                                                sA1, sA2, sB1, sB2, sC1, sC2, sAdd2);
}

extern "C" void kernel_launch(void* const* d_in, const int* in_sizes, int n_in,
                              void* d_out, int out_size)
{
    const int*   tokens  = (const int*)  d_in[0];
    const float* memory  = (const float*)d_in[1];
    const float* embed   = (const float*)d_in[2];
    const float* Wq      = (const float*)d_in[3];
    const float* Wkv     = (const float*)d_in[4];
    const float* Wr      = (const float*)d_in[5];
    const float* Wo      = (const float*)d_in[6];
    const float* bq      = (const float*)d_in[7];
    const float* bkv     = (const float*)d_in[8];
    const float* br      = (const float*)d_in[9];
    const float* bo      = (const float*)d_in[10];
    const float* bias_c  = (const float*)d_in[11];
    const float* bias_r  = (const float*)d_in[12];
    const float* ln1_g   = (const float*)d_in[13];
    const float* ln1_b   = (const float*)d_in[14];
    const float* W1      = (const float*)d_in[15];
    const float* b1      = (const float*)d_in[16];
    const float* W2      = (const float*)d_in[17];
    const float* b2      = (const float*)d_in[18];
    const float* ln2_g   = (const float*)d_in[19];
    const float* ln2_b   = (const float*)d_in[20];
    const float* Wout    = (const float*)d_in[21];
    const float* bout    = (const float*)d_in[22];
    float* out = (float*)d_out;

    float *x, *full, *q, *kv, *rel, *r, *ac, *ar, *ctx, *tmp, *h1, *ff, *h2;
    cudaGetSymbolAddress((void**)&x,    g_x);
    cudaGetSymbolAddress((void**)&full, g_full);
    cudaGetSymbolAddress((void**)&q,    g_q);
    cudaGetSymbolAddress((void**)&kv,   g_kv);
    cudaGetSymbolAddress((void**)&rel,  g_rel);
    cudaGetSymbolAddress((void**)&r,    g_r);
    cudaGetSymbolAddress((void**)&ac,   g_ac);
    cudaGetSymbolAddress((void**)&ar,   g_ar);
    cudaGetSymbolAddress((void**)&ctx,  g_ctx);
    cudaGetSymbolAddress((void**)&tmp,  g_tmp);
    cudaGetSymbolAddress((void**)&h1,   g_h1);
    cudaGetSymbolAddress((void**)&ff,   g_ff);
    cudaGetSymbolAddress((void**)&h2,   g_h2);

    const int M_TOK = BB * SS;      // 2048
    const int M_FULL = BB * KLEN;   // 3200

    // 1) embedding + concat(memory, x)
    {
        long long tot = (long long)BB * KLEN * UU;
        build_full<<<(unsigned)((tot + 255) / 256), 256>>>(tokens, memory, embed, x, full);
    }
    // 2) sinusoidal relative positions
    {
        long long tot = (long long)KLEN * UU;
        pos_embed<<<(unsigned)((tot + 255) / 256), 256>>>(rel);
    }
    // 3) q = x@Wq + bq
    launch_gemm(false, false, x, Wq, q, bq, nullptr,
                M_TOK, UU, UU, UU, UU, UU, 1, 1, 0,0,0,0,0,0,0);
    // 4) kv = full@Wkv + bkv
    launch_gemm(false, false, full, Wkv, kv, bkv, nullptr,
                M_FULL, 2*UU, UU, UU, 2*UU, 2*UU, 1, 1, 0,0,0,0,0,0,0);
    // 5) r = rel@Wr + br
    launch_gemm(false, false, rel, Wr, r, br, nullptr,
                KLEN, UU, UU, UU, UU, UU, 1, 1, 0,0,0,0,0,0,0);
    // 6) content scores: ac[b,h,i,j] = (q+u)[b,i,h,:] . k[b,j,h,:]
    launch_gemm(true, false, q, kv, ac, nullptr, bias_c,
                SS, KLEN, DD, UU, 2*UU, KLEN,
                BB*HH, HH,
                (long long)SS*UU, 64,
                (long long)KLEN*2*UU, 64,
                (long long)HH*SS*KLEN, (long long)SS*KLEN,
                64);
    // 7) position scores (unshifted): ar[b,h,i,jj] = (q+v)[b,i,h,:] . r[jj,h,:]
    launch_gemm(true, false, q, r, ar, nullptr, bias_r,
                SS, KLEN, DD, UU, UU, KLEN,
                BB*HH, HH,
                (long long)SS*UU, 64,
                0, 64,
                (long long)HH*SS*KLEN, (long long)SS*KLEN,
                64);
    // 8) fused rel-shift + mask + softmax (in place on ac)
    {
        dim3 grid(SS, BB * HH);
        attn_softmax<<<grid, 256>>>(ac, ar);
    }
    // 9) ctx[b,i,h,:] = sum_j P[b,h,i,j] * v[b,j,h,:]
    launch_gemm(false, false, ac, kv + UU, ctx, nullptr, nullptr,
                SS, DD, KLEN, KLEN, 2*UU, UU,
                BB*HH, HH,
                (long long)HH*SS*KLEN, (long long)SS*KLEN,
                (long long)KLEN*2*UU, 64,
                (long long)SS*UU, 64,
                0);
    // 10) attention output projection
    launch_gemm(false, false, ctx, Wo, tmp, bo, nullptr,
                M_TOK, UU, UU, UU, UU, UU, 1, 1, 0,0,0,0,0,0,0);
    // 11) h1 = LN(x + attn_out)
    add_ln<<<M_TOK, 256>>>(x, tmp, ln1_g, ln1_b, h1);
    // 12) ff = relu(h1@W1 + b1)
    launch_gemm(false, true, h1, W1, ff, b1, nullptr,
                M_TOK, FFD, UU, UU, FFD, FFD, 1, 1, 0,0,0,0,0,0,0);
    // 13) ff2 = ff@W2 + b2
    launch_gemm(false, false, ff, W2, tmp, b2, nullptr,
                M_TOK, UU, FFD, FFD, UU, UU, 1, 1, 0,0,0,0,0,0,0);
    // 14) h2 = LN(h1 + ff2)
    add_ln<<<M_TOK, 256>>>(h1, tmp, ln2_g, ln2_b, h2);
    // 15) logits = h2@Wout + bout -> d_out
    launch_gemm(false, false, h2, Wout, out, bout, nullptr,
                M_TOK, NT, UU, UU, NT, NT, 1, 1, 0,0,0,0,0,0,0);
    // 16) softmax over vocab, in place
    softmax_rows<<<M_TOK, 512>>>(out, NT);
}

// round 4
// speedup vs baseline: 2.8811x; 1.6734x over previous
#include <cuda_runtime.h>
#include <cuda_bf16.h>
#include <math.h>
#include <stdint.h>

// ---------------- problem constants ----------------
#define BB 2
#define SS 1024
#define UU 1024
#define HH 16
#define DD 64
#define NT 32000
#define MEMLEN 576
#define FFD 4096
#define KLEN 1600   // MEM + S
#define VOCAB 1024

typedef __nv_bfloat16 bf16;

// ---------------- scratch (device globals; no allocation allowed) ----------------
__device__ float g_x   [(size_t)BB*SS*UU];
__device__ float g_q   [(size_t)BB*SS*UU];
__device__ float g_kv  [(size_t)BB*KLEN*2*UU];
__device__ float g_r   [(size_t)KLEN*UU];
__device__ float g_ac  [(size_t)BB*HH*SS*KLEN];
__device__ float g_ar  [(size_t)BB*HH*SS*KLEN];
__device__ float g_ctx [(size_t)BB*SS*UU];
__device__ float g_tmp [(size_t)BB*SS*UU];
__device__ float g_h1  [(size_t)BB*SS*UU];
__device__ float g_h2  [(size_t)BB*SS*UU];

// bf16 hi/lo split buffers (A-side, K-major)
__device__ bf16 g_xh   [(size_t)BB*SS*UU],   g_xl   [(size_t)BB*SS*UU];
__device__ bf16 g_fullh[(size_t)BB*KLEN*UU], g_fulll[(size_t)BB*KLEN*UU];
__device__ bf16 g_relh [(size_t)KLEN*UU],    g_rell [(size_t)KLEN*UU];
__device__ bf16 g_ctxh [(size_t)BB*SS*UU],   g_ctxl [(size_t)BB*SS*UU];
__device__ bf16 g_h1h  [(size_t)BB*SS*UU],   g_h1l  [(size_t)BB*SS*UU];
__device__ bf16 g_h2h  [(size_t)BB*SS*UU],   g_h2l  [(size_t)BB*SS*UU];
__device__ bf16 g_ffh  [(size_t)BB*SS*FFD],  g_ffl  [(size_t)BB*SS*FFD];
// transposed weights [N,K] bf16 hi/lo
__device__ bf16 g_WqTh [(size_t)UU*UU],    g_WqTl [(size_t)UU*UU];
__device__ bf16 g_WkvTh[(size_t)2*UU*UU],  g_WkvTl[(size_t)2*UU*UU];
__device__ bf16 g_WrTh [(size_t)UU*UU],    g_WrTl [(size_t)UU*UU];
__device__ bf16 g_WoTh [(size_t)UU*UU],    g_WoTl [(size_t)UU*UU];
__device__ bf16 g_W1Th [(size_t)FFD*UU],   g_W1Tl [(size_t)FFD*UU];
__device__ bf16 g_W2Th [(size_t)UU*FFD],   g_W2Tl [(size_t)UU*FFD];
__device__ bf16 g_WoutTh[(size_t)NT*UU],   g_WoutTl[(size_t)NT*UU];

// ---------------- helpers ----------------
__device__ __forceinline__ uint32_t smem_u32(const void* p) {
    uint32_t a;
    asm("{ .reg .u64 t; cvta.to.shared.u64 t, %1; cvt.u32.u64 %0, t; }" : "=r"(a) : "l"(p));
    return a;
}
__device__ __forceinline__ void split_val(float v, bf16& h, bf16& l) {
    h = __float2bfloat16(v);
    l = __float2bfloat16(v - __bfloat162float(h));
}
__device__ __forceinline__ void cp16(uint32_t dst, const void* src) {
    asm volatile("cp.async.cg.shared.global [%0], [%1], 16;" :: "r"(dst), "l"(src));
}
__device__ __forceinline__ void ldx4(uint32_t* r, uint32_t addr) {
    asm volatile("ldmatrix.sync.aligned.m8n8.x4.shared.b16 {%0,%1,%2,%3}, [%4];"
                 : "=r"(r[0]), "=r"(r[1]), "=r"(r[2]), "=r"(r[3]) : "r"(addr));
}
__device__ __forceinline__ void ldx2(uint32_t* r, uint32_t addr) {
    asm volatile("ldmatrix.sync.aligned.m8n8.x2.shared.b16 {%0,%1}, [%2];"
                 : "=r"(r[0]), "=r"(r[1]) : "r"(addr));
}
__device__ __forceinline__ void mma16816(float* c, const uint32_t* a, const uint32_t* b) {
    asm volatile("mma.sync.aligned.m16n8k16.row.col.f32.bf16.bf16.f32 "
                 "{%0,%1,%2,%3}, {%4,%5,%6,%7}, {%8,%9}, {%0,%1,%2,%3};"
                 : "+f"(c[0]), "+f"(c[1]), "+f"(c[2]), "+f"(c[3])
                 : "r"(a[0]), "r"(a[1]), "r"(a[2]), "r"(a[3]), "r"(b[0]), "r"(b[1]));
}

// ---------------- HMMA split-bf16 GEMM ----------------
// C[M,N] = (Ah+Al)[M,K] @ (Bh+Bl)[N,K]^T + bias   (3-pass: hh + hl + lh)
// Requirements: N % 128 == 0, K % 16 == 0.  M arbitrary (clamped loads, guarded stores).
// OUT: 0 = fp32 C ; 2 = relu then bf16 hi/lo split to Ch/Cl.
// CTA 128x128, 256 threads, 8 warps of 64x32. kb=16, 3-stage cp.async pipeline.
// smem per stage: 4 arrays (Ah,Al,Bh,Bl) x 128 rows x 32B = 16 KB; 3 stages = 48 KB.
// Swizzle: within a 32B row, 16B chunk c stored at c ^ ((row>>2)&1).
template<int OUT>
__global__ __launch_bounds__(256)
void hgemm(const bf16* __restrict__ Ah, const bf16* __restrict__ Al,
           const bf16* __restrict__ Bh, const bf16* __restrict__ Bl,
           float* __restrict__ C, bf16* __restrict__ Ch, bf16* __restrict__ Cl,
           const float* __restrict__ bias, int M, int N, int K)
{
    __shared__ __align__(128) char sm[3 * 4 * 4096];
    const uint32_t smb = smem_u32(sm);
    const int tid = threadIdx.x, wid = tid >> 5, lane = tid & 31;
    const int m0 = blockIdx.y * 128, n0 = blockIdx.x * 128;
    const int m_w = (wid & 1) * 64, n_w = (wid >> 1) * 32;

    // cp.async load of chunk cc into stage s (one 16B per array per thread)
    const int lr = tid >> 1, lc = tid & 1;
    const uint32_t so = (uint32_t)(lr * 32 + ((lc ^ ((lr >> 2) & 1)) << 4));
    const int ga = min(m0 + lr, M - 1);
    const int gb = n0 + lr;                    // N % 128 == 0, always valid
    const long long aoff = (long long)ga * K + lc * 8;
    const long long boff = (long long)gb * K + lc * 8;

    float acc[4][4][4];
    #pragma unroll
    for (int i = 0; i < 4; i++)
        #pragma unroll
        for (int j = 0; j < 4; j++)
            #pragma unroll
            for (int k = 0; k < 4; k++) acc[i][j][k] = 0.f;

    const int NC = K / 16;   // >= 4 at all call sites

    // prologue: chunks 0, 1
    {
        cp16(smb + 0*16384 + 0*4096 + so, Ah + aoff);
        cp16(smb + 0*16384 + 1*4096 + so, Al + aoff);
        cp16(smb + 0*16384 + 2*4096 + so, Bh + boff);
        cp16(smb + 0*16384 + 3*4096 + so, Bl + boff);
        asm volatile("cp.async.commit_group;");
        cp16(smb + 1*16384 + 0*4096 + so, Ah + aoff + 16);
        cp16(smb + 1*16384 + 1*4096 + so, Al + aoff + 16);
        cp16(smb + 1*16384 + 2*4096 + so, Bh + boff + 16);
        cp16(smb + 1*16384 + 3*4096 + so, Bl + boff + 16);
        asm volatile("cp.async.commit_group;");
    }

    const int rr = lane & 15, ccq = lane >> 4;     // A ldmatrix lane mapping
    const int rb = lane & 7,  cb  = (lane >> 3) & 1; // B ldmatrix lane mapping

    for (int c = 0; c < NC; c++) {
        if (c + 2 < NC) {
            const uint32_t st = smb + ((c + 2) % 3) * 16384;
            const long long k0 = (long long)(c + 2) * 16;
            cp16(st + 0*4096 + so, Ah + aoff + k0);
            cp16(st + 1*4096 + so, Al + aoff + k0);
            cp16(st + 2*4096 + so, Bh + boff + k0);
            cp16(st + 3*4096 + so, Bl + boff + k0);
        }
        asm volatile("cp.async.commit_group;");
        asm volatile("cp.async.wait_group 2;");
        __syncthreads();

        const uint32_t st = smb + (c % 3) * 16384;
        uint32_t ah[4][4], al[4][4], bh[4][2], bl[4][2];
        #pragma unroll
        for (int mt = 0; mt < 4; mt++) {
            int R = m_w + mt * 16 + rr;
            uint32_t ad = st + R * 32 + ((ccq ^ ((R >> 2) & 1)) << 4);
            ldx4(ah[mt], ad);
            ldx4(al[mt], ad + 4096);
        }
        #pragma unroll
        for (int nt = 0; nt < 4; nt++) {
            int Nr = n_w + nt * 8 + rb;
            uint32_t bd = st + 8192 + Nr * 32 + ((cb ^ ((Nr >> 2) & 1)) << 4);
            ldx2(bh[nt], bd);
            ldx2(bl[nt], bd + 4096);
        }
        #pragma unroll
        for (int mt = 0; mt < 4; mt++)
            #pragma unroll
            for (int nt = 0; nt < 4; nt++) {
                mma16816(acc[mt][nt], ah[mt], bh[nt]);
                mma16816(acc[mt][nt], ah[mt], bl[nt]);
                mma16816(acc[mt][nt], al[mt], bh[nt]);
            }
        __syncthreads();
    }

    // ---- epilogue ----
    #pragma unroll
    for (int mt = 0; mt < 4; mt++) {
        int gm0 = m0 + m_w + mt * 16 + (lane >> 2);
        #pragma unroll
        for (int nt = 0; nt < 4; nt++) {
            int gn = n0 + n_w + nt * 8 + (lane & 3) * 2;
            float2 bv = *(const float2*)(bias + gn);
            float v0 = acc[mt][nt][0] + bv.x;
            float v1 = acc[mt][nt][1] + bv.y;
            float v2 = acc[mt][nt][2] + bv.x;
            float v3 = acc[mt][nt][3] + bv.y;
            if (OUT == 0) {
                if (gm0 < M) {
                    float2 w0; w0.x = v0; w0.y = v1;
                    *(float2*)(C + (long long)gm0 * N + gn) = w0;
                }
                if (gm0 + 8 < M) {
                    float2 w1; w1.x = v2; w1.y = v3;
                    *(float2*)(C + (long long)(gm0 + 8) * N + gn) = w1;
                }
            } else {
                v0 = fmaxf(v0, 0.f); v1 = fmaxf(v1, 0.f);
                v2 = fmaxf(v2, 0.f); v3 = fmaxf(v3, 0.f);
                bf16 h0, l0, h1, l1;
                if (gm0 < M) {
                    long long o = (long long)gm0 * N + gn;
                    split_val(v0, h0, l0); split_val(v1, h1, l1);
                    __nv_bfloat162 ph; ph.x = h0; ph.y = h1;
                    __nv_bfloat162 pl; pl.x = l0; pl.y = l1;
                    *(__nv_bfloat162*)(Ch + o) = ph;
                    *(__nv_bfloat162*)(Cl + o) = pl;
                }
                if (gm0 + 8 < M) {
                    long long o = (long long)(gm0 + 8) * N + gn;
                    split_val(v2, h0, l0); split_val(v3, h1, l1);
                    __nv_bfloat162 ph; ph.x = h0; ph.y = h1;
                    __nv_bfloat162 pl; pl.x = l0; pl.y = l1;
                    *(__nv_bfloat162*)(Ch + o) = ph;
                    *(__nv_bfloat162*)(Cl + o) = pl;
                }
            }
        }
    }
}

// ---------------- reductions ----------------
__device__ __forceinline__ float block_reduce_sum(float v) {
    __shared__ float sm[16];
    __syncthreads();
    #pragma unroll
    for (int o = 16; o > 0; o >>= 1) v += __shfl_xor_sync(0xffffffffu, v, o);
    if ((threadIdx.x & 31) == 0) sm[threadIdx.x >> 5] = v;
    __syncthreads();
    if (threadIdx.x < 32) {
        float x = (threadIdx.x < (blockDim.x >> 5)) ? sm[threadIdx.x] : 0.f;
        #pragma unroll
        for (int o = 8; o > 0; o >>= 1) x += __shfl_xor_sync(0xffffffffu, x, o);
        if (threadIdx.x == 0) sm[0] = x;
    }
    __syncthreads();
    return sm[0];
}
__device__ __forceinline__ float block_reduce_max(float v) {
    __shared__ float sm[16];
    __syncthreads();
    #pragma unroll
    for (int o = 16; o > 0; o >>= 1) v = fmaxf(v, __shfl_xor_sync(0xffffffffu, v, o));
    if ((threadIdx.x & 31) == 0) sm[threadIdx.x >> 5] = v;
    __syncthreads();
    if (threadIdx.x < 32) {
        float x = (threadIdx.x < (blockDim.x >> 5)) ? sm[threadIdx.x] : -3.4e38f;
        #pragma unroll
        for (int o = 8; o > 0; o >>= 1) x = fmaxf(x, __shfl_xor_sync(0xffffffffu, x, o));
        if (threadIdx.x == 0) sm[0] = x;
    }
    __syncthreads();
    return sm[0];
}

// ---------------- SIMT SGEMM (attention-only paths) ----------------
template <int BN, bool TRANSB>
__global__ __launch_bounds__(256, 2)
void sgemm2(const float* __restrict__ A, const float* __restrict__ B,
            float* __restrict__ C, const float* __restrict__ aadd,
            int M, int N, int K, int lda, int ldb, int ldc,
            int Z2,
            long long sA1, long long sA2, long long sB1, long long sB2,
            long long sC1, long long sC2, long long sAdd2)
{
    constexpr int BM = 128, BK = 16;
    constexpr int TM = 8, TN = BN / 16;
    constexpr int A4 = (BM * BK) / 4 / 256;
    constexpr int B4 = (BN * BK) / 4 / 256;

    __shared__ float As[2][BK][BM + 4];
    __shared__ float Bs[2][BK][BN + 4];

    const int tid = threadIdx.x;
    const int tx = tid & 15, ty = tid >> 4;
    const int m0 = blockIdx.y * BM, n0 = blockIdx.x * BN;
    const int z  = blockIdx.z;
    const int z1 = z / Z2, z2 = z - z1 * Z2;
    A += z1 * sA1 + z2 * sA2;
    B += z1 * sB1 + z2 * sB2;
    C += z1 * sC1 + z2 * sC2;
    if (aadd) aadd += z2 * sAdd2;

    float acc[TM][TN];
    #pragma unroll
    for (int i = 0; i < TM; i++)
        #pragma unroll
        for (int j = 0; j < TN; j++) acc[i][j] = 0.f;

    float4 ra[A4], rb[B4];
    const int nk = K / BK;

    #pragma unroll
    for (int i = 0; i < A4; i++) {
        int e = tid + i * 256;
        int m = e >> 2, kq = e & 3;
        int gm = min(m0 + m, M - 1);
        float4 v = *(const float4*)(A + (long long)gm * lda + kq * 4);
        if (aadd) {
            float4 ad = *(const float4*)(aadd + kq * 4);
            v.x += ad.x; v.y += ad.y; v.z += ad.z; v.w += ad.w;
        }
        ra[i] = v;
    }
    #pragma unroll
    for (int i = 0; i < B4; i++) {
        int e = tid + i * 256;
        if (!TRANSB) {
            int kk = e / (BN / 4), nq = e % (BN / 4);
            int gn = min(n0 + nq * 4, N - 4);
            rb[i] = *(const float4*)(B + (long long)kk * ldb + gn);
        } else {
            int n = e >> 2, kq = e & 3;
            int gn = min(n0 + n, N - 1);
            rb[i] = *(const float4*)(B + (long long)gn * ldb + kq * 4);
        }
    }
    #pragma unroll
    for (int i = 0; i < A4; i++) {
        int e = tid + i * 256;
        int m = e >> 2, kq = e & 3;
        As[0][kq * 4 + 0][m] = ra[i].x;
        As[0][kq * 4 + 1][m] = ra[i].y;
        As[0][kq * 4 + 2][m] = ra[i].z;
        As[0][kq * 4 + 3][m] = ra[i].w;
    }
    #pragma unroll
    for (int i = 0; i < B4; i++) {
        int e = tid + i * 256;
        if (!TRANSB) {
            int kk = e / (BN / 4), nq = e % (BN / 4);
            *(float4*)&Bs[0][kk][nq * 4] = rb[i];
        } else {
            int n = e >> 2, kq = e & 3;
            Bs[0][kq * 4 + 0][n] = rb[i].x;
            Bs[0][kq * 4 + 1][n] = rb[i].y;
            Bs[0][kq * 4 + 2][n] = rb[i].z;
            Bs[0][kq * 4 + 3][n] = rb[i].w;
        }
    }
    __syncthreads();

    int buf = 0;
    for (int t = 0; t < nk; t++) {
        if (t + 1 < nk) {
            const int k0 = (t + 1) * BK;
            #pragma unroll
            for (int i = 0; i < A4; i++) {
                int e = tid + i * 256;
                int m = e >> 2, kq = e & 3;
                int gm = min(m0 + m, M - 1);
                float4 v = *(const float4*)(A + (long long)gm * lda + k0 + kq * 4);
                if (aadd) {
                    float4 ad = *(const float4*)(aadd + k0 + kq * 4);
                    v.x += ad.x; v.y += ad.y; v.z += ad.z; v.w += ad.w;
                }
                ra[i] = v;
            }
            #pragma unroll
            for (int i = 0; i < B4; i++) {
                int e = tid + i * 256;
                if (!TRANSB) {
                    int kk = e / (BN / 4), nq = e % (BN / 4);
                    int gn = min(n0 + nq * 4, N - 4);
                    rb[i] = *(const float4*)(B + (long long)(k0 + kk) * ldb + gn);
                } else {
                    int n = e >> 2, kq = e & 3;
                    int gn = min(n0 + n, N - 1);
                    rb[i] = *(const float4*)(B + (long long)gn * ldb + k0 + kq * 4);
                }
            }
        }
        #pragma unroll
        for (int kk = 0; kk < BK; kk++) {
            float a[TM], b[TN];
            *(float4*)&a[0] = *(const float4*)&As[buf][kk][ty * TM];
            *(float4*)&a[4] = *(const float4*)&As[buf][kk][ty * TM + 4];
            *(float4*)&b[0] = *(const float4*)&Bs[buf][kk][tx * TN];
            if (TN == 8)
                *(float4*)&b[4] = *(const float4*)&Bs[buf][kk][tx * TN + 4];
            #pragma unroll
            for (int i = 0; i < TM; i++)
                #pragma unroll
                for (int j = 0; j < TN; j++)
                    acc[i][j] = fmaf(a[i], b[j], acc[i][j]);
        }
        if (t + 1 < nk) {
            int nb = buf ^ 1;
            #pragma unroll
            for (int i = 0; i < A4; i++) {
                int e = tid + i * 256;
                int m = e >> 2, kq = e & 3;
                As[nb][kq * 4 + 0][m] = ra[i].x;
                As[nb][kq * 4 + 1][m] = ra[i].y;
                As[nb][kq * 4 + 2][m] = ra[i].z;
                As[nb][kq * 4 + 3][m] = ra[i].w;
            }
            #pragma unroll
            for (int i = 0; i < B4; i++) {
                int e = tid + i * 256;
                if (!TRANSB) {
                    int kk = e / (BN / 4), nq = e % (BN / 4);
                    *(float4*)&Bs[nb][kk][nq * 4] = rb[i];
                } else {
                    int n = e >> 2, kq = e & 3;
                    Bs[nb][kq * 4 + 0][n] = rb[i].x;
                    Bs[nb][kq * 4 + 1][n] = rb[i].y;
                    Bs[nb][kq * 4 + 2][n] = rb[i].z;
                    Bs[nb][kq * 4 + 3][n] = rb[i].w;
                }
            }
        }
        __syncthreads();
        buf ^= 1;
    }

    #pragma unroll
    for (int i = 0; i < TM; i++) {
        int gm = m0 + ty * TM + i;
        if (gm >= M) continue;
        #pragma unroll
        for (int j4 = 0; j4 < TN / 4; j4++) {
            int gn = n0 + tx * TN + j4 * 4;
            if (gn >= N) continue;
            float4 v;
            v.x = acc[i][j4 * 4 + 0];
            v.y = acc[i][j4 * 4 + 1];
            v.z = acc[i][j4 * 4 + 2];
            v.w = acc[i][j4 * 4 + 3];
            *(float4*)(C + (long long)gm * ldc + gn) = v;
        }
    }
}

// ---------------- small kernels ----------------
__global__ void build_full(const int* __restrict__ tokens,
                           const float* __restrict__ memory,
                           const float* __restrict__ embed,
                           float* __restrict__ x,
                           bf16* __restrict__ xh, bf16* __restrict__ xl,
                           bf16* __restrict__ fullh, bf16* __restrict__ fulll)
{
    long long idx = (long long)blockIdx.x * 256 + threadIdx.x;
    const long long tot = (long long)BB * KLEN * UU;
    if (idx >= tot) return;
    int u = (int)(idx % UU);
    long long t = idx / UU;
    int j = (int)(t % KLEN);
    int b = (int)(t / KLEN);
    float v;
    if (j < MEMLEN) {
        v = memory[((long long)b * MEMLEN + j) * UU + u];
    } else {
        int s = j - MEMLEN;
        int tok = tokens[b * SS + s];
        v = embed[(long long)tok * UU + u] * 32.0f;  // sqrt(1024)
        long long xo = ((long long)b * SS + s) * UU + u;
        x[xo] = v;
        bf16 h, l; split_val(v, h, l);
        xh[xo] = h; xl[xo] = l;
    }
    bf16 h, l; split_val(v, h, l);
    fullh[idx] = h; fulll[idx] = l;
}

__global__ void pos_embed(bf16* __restrict__ relh, bf16* __restrict__ rell)
{
    long long idx = (long long)blockIdx.x * 256 + threadIdx.x;
    if (idx >= (long long)KLEN * UU) return;
    int u = (int)(idx % UU);
    int jj = (int)(idx / UU);
    float pos = (float)(KLEN - 1 - jj);
    int i2 = (u < UU / 2) ? u : (u - UU / 2);
    float expo = ((float)(2 * i2)) / (float)UU;
    float invf = expf(-expo * 9.210340371976184f);  // ln(10000)
    float ang = pos * invf;
    float v = (u < UU / 2) ? sinf(ang) : cosf(ang);
    bf16 h, l; split_val(v, h, l);
    relh[idx] = h; rell[idx] = l;
}

// transpose + split: W[K,N] fp32 -> hi/lo[N,K] bf16 (K,N multiples of 32)
__global__ void split_T(const float* __restrict__ W, bf16* __restrict__ hi,
                        bf16* __restrict__ lo, int K, int N)
{
    __shared__ float t[32][33];
    int n0 = blockIdx.x * 32, k0 = blockIdx.y * 32;
    #pragma unroll
    for (int i = 0; i < 32; i += 8)
        t[threadIdx.y + i][threadIdx.x] =
            W[(long long)(k0 + threadIdx.y + i) * N + n0 + threadIdx.x];
    __syncthreads();
    #pragma unroll
    for (int i = 0; i < 32; i += 8) {
        float v = t[threadIdx.x][threadIdx.y + i];
        long long o = (long long)(n0 + threadIdx.y + i) * K + k0 + threadIdx.x;
        bf16 h, l; split_val(v, h, l);
        hi[o] = h; lo[o] = l;
    }
}

__global__ void split_rows(const float* __restrict__ src, bf16* __restrict__ hi,
                           bf16* __restrict__ lo, long long n)
{
    long long idx = (long long)blockIdx.x * 256 + threadIdx.x;
    if (idx >= n) return;
    bf16 h, l; split_val(src[idx], h, l);
    hi[idx] = h; lo[idx] = l;
}

// mask + rel-shift + softmax, in place on ac.
__global__ __launch_bounds__(256)
void attn_softmax(float* __restrict__ ac, const float* __restrict__ ar)
{
    int i = blockIdx.x;
    long long z = blockIdx.y;
    float* row = ac + (z * SS + i) * (long long)KLEN;
    const float* arow = ar + (z * SS + i) * (long long)KLEN;
    int lim = i + MEMLEN;
    int shift = SS - 1 - i;
    int tid = threadIdx.x;

    float lmax = -3.4e38f;
    for (int j = tid; j <= lim; j += 256) {
        float v = (row[j] + arow[j + shift]) * 0.125f;
        row[j] = v;
        lmax = fmaxf(lmax, v);
    }
    float m = block_reduce_max(lmax);
    float lsum = 0.f;
    for (int j = tid; j <= lim; j += 256) {
        float e = expf(row[j] - m);
        row[j] = e;
        lsum += e;
    }
    float s = block_reduce_sum(lsum);
    float inv = 1.f / s;
    for (int j = tid; j <= lim; j += 256) row[j] *= inv;
    for (int j = lim + 1 + tid; j < KLEN; j += 256) row[j] = 0.f;
}

__global__ __launch_bounds__(256)
void add_ln(const float* __restrict__ a, const float* __restrict__ b,
            const float* __restrict__ g, const float* __restrict__ beta,
            float* __restrict__ out, bf16* __restrict__ oh, bf16* __restrict__ ol)
{
    long long row = blockIdx.x;
    const float* pa = a + row * UU;
    const float* pb = b + row * UU;
    int tid = threadIdx.x;
    float vals[4];
    float s = 0.f, ss = 0.f;
    #pragma unroll
    for (int t = 0; t < 4; t++) {
        int idx = tid * 4 + t;
        float v = pa[idx] + pb[idx];
        vals[t] = v;
        s += v;
        ss += v * v;
    }
    s = block_reduce_sum(s);
    ss = block_reduce_sum(ss);
    float mean = s * (1.f / UU);
    float var = fmaxf(ss * (1.f / UU) - mean * mean, 0.f);
    float rstd = rsqrtf(var + 1e-5f);
    #pragma unroll
    for (int t = 0; t < 4; t++) {
        int idx = tid * 4 + t;
        float v = (vals[t] - mean) * rstd * g[idx] + beta[idx];
        out[row * UU + idx] = v;
        bf16 h, l; split_val(v, h, l);
        oh[row * UU + idx] = h; ol[row * UU + idx] = l;
    }
}

__global__ __launch_bounds__(512)
void softmax_rows(float* __restrict__ x, int N)
{
    long long row = blockIdx.x;
    float* p = x + row * (long long)N;
    int tid = threadIdx.x;
    float lmax = -3.4e38f;
    for (int j = tid; j < N; j += 512) lmax = fmaxf(lmax, p[j]);
    float m = block_reduce_max(lmax);
    float lsum = 0.f;
    for (int j = tid; j < N; j += 512) {
        float e = expf(p[j] - m);
        p[j] = e;
        lsum += e;
    }
    float s = block_reduce_sum(lsum);
    float inv = 1.f / s;
    for (int j = tid; j < N; j += 512) p[j] *= inv;
}

// ---------------- host ----------------
static void launch_hgemm(int outmode, const bf16* Ah, const bf16* Al,
                         const bf16* Bh, const bf16* Bl,
                         float* C, bf16* Ch, bf16* Cl, const float* bias,
                         int M, int N, int K)
{
    dim3 grid(N / 128, (M + 127) / 128);
    if (outmode == 0)
        hgemm<0><<<grid, 256>>>(Ah, Al, Bh, Bl, C, Ch, Cl, bias, M, N, K);
    else
        hgemm<2><<<grid, 256>>>(Ah, Al, Bh, Bl, C, Ch, Cl, bias, M, N, K);
}

extern "C" void kernel_launch(void* const* d_in, const int* in_sizes, int n_in,
                              void* d_out, int out_size)
{
    const int*   tokens  = (const int*)  d_in[0];
    const float* memory  = (const float*)d_in[1];
    const float* embed   = (const float*)d_in[2];
    const float* Wq      = (const float*)d_in[3];
    const float* Wkv     = (const float*)d_in[4];
    const float* Wr      = (const float*)d_in[5];
    const float* Wo      = (const float*)d_in[6];
    const float* bq      = (const float*)d_in[7];
    const float* bkv     = (const float*)d_in[8];
    const float* br      = (const float*)d_in[9];
    const float* bo      = (const float*)d_in[10];
    const float* bias_c  = (const float*)d_in[11];
    const float* bias_r  = (const float*)d_in[12];
    const float* ln1_g   = (const float*)d_in[13];
    const float* ln1_b   = (const float*)d_in[14];
    const float* W1      = (const float*)d_in[15];
    const float* b1      = (const float*)d_in[16];
    const float* W2      = (const float*)d_in[17];
    const float* b2      = (const float*)d_in[18];
    const float* ln2_g   = (const float*)d_in[19];
    const float* ln2_b   = (const float*)d_in[20];
    const float* Wout    = (const float*)d_in[21];
    const float* bout    = (const float*)d_in[22];
    float* out = (float*)d_out;

    float *x, *q, *kv, *r, *ac, *ar, *ctx, *tmp, *h1, *h2;
    cudaGetSymbolAddress((void**)&x,   g_x);
    cudaGetSymbolAddress((void**)&q,   g_q);
    cudaGetSymbolAddress((void**)&kv,  g_kv);
    cudaGetSymbolAddress((void**)&r,   g_r);
    cudaGetSymbolAddress((void**)&ac,  g_ac);
    cudaGetSymbolAddress((void**)&ar,  g_ar);
    cudaGetSymbolAddress((void**)&ctx, g_ctx);
    cudaGetSymbolAddress((void**)&tmp, g_tmp);
    cudaGetSymbolAddress((void**)&h1,  g_h1);
    cudaGetSymbolAddress((void**)&h2,  g_h2);

    bf16 *xh,*xl,*fullh,*fulll,*relh,*rell,*ctxh,*ctxl,*h1h,*h1l,*h2h,*h2l,*ffh,*ffl;
    cudaGetSymbolAddress((void**)&xh, g_xh);     cudaGetSymbolAddress((void**)&xl, g_xl);
    cudaGetSymbolAddress((void**)&fullh, g_fullh); cudaGetSymbolAddress((void**)&fulll, g_fulll);
    cudaGetSymbolAddress((void**)&relh, g_relh); cudaGetSymbolAddress((void**)&rell, g_rell);
    cudaGetSymbolAddress((void**)&ctxh, g_ctxh); cudaGetSymbolAddress((void**)&ctxl, g_ctxl);
    cudaGetSymbolAddress((void**)&h1h, g_h1h);   cudaGetSymbolAddress((void**)&h1l, g_h1l);
    cudaGetSymbolAddress((void**)&h2h, g_h2h);   cudaGetSymbolAddress((void**)&h2l, g_h2l);
    cudaGetSymbolAddress((void**)&ffh, g_ffh);   cudaGetSymbolAddress((void**)&ffl, g_ffl);

    bf16 *WqTh,*WqTl,*WkvTh,*WkvTl,*WrTh,*WrTl,*WoTh,*WoTl,*W1Th,*W1Tl,*W2Th,*W2Tl,*WoutTh,*WoutTl;
    cudaGetSymbolAddress((void**)&WqTh, g_WqTh);   cudaGetSymbolAddress((void**)&WqTl, g_WqTl);
    cudaGetSymbolAddress((void**)&WkvTh, g_WkvTh); cudaGetSymbolAddress((void**)&WkvTl, g_WkvTl);
    cudaGetSymbolAddress((void**)&WrTh, g_WrTh);   cudaGetSymbolAddress((void**)&WrTl, g_WrTl);
    cudaGetSymbolAddress((void**)&WoTh, g_WoTh);   cudaGetSymbolAddress((void**)&WoTl, g_WoTl);
    cudaGetSymbolAddress((void**)&W1Th, g_W1Th);   cudaGetSymbolAddress((void**)&W1Tl, g_W1Tl);
    cudaGetSymbolAddress((void**)&W2Th, g_W2Th);   cudaGetSymbolAddress((void**)&W2Tl, g_W2Tl);
    cudaGetSymbolAddress((void**)&WoutTh, g_WoutTh); cudaGetSymbolAddress((void**)&WoutTl, g_WoutTl);

    const int M_TOK = BB * SS;      // 2048
    const int M_FULL = BB * KLEN;   // 3200

    // 1) embedding + concat + splits
    {
        long long tot = (long long)BB * KLEN * UU;
        build_full<<<(unsigned)((tot + 255) / 256), 256>>>(tokens, memory, embed,
                                                           x, xh, xl, fullh, fulll);
    }
    // 2) positional embedding (split only)
    {
        long long tot = (long long)KLEN * UU;
        pos_embed<<<(unsigned)((tot + 255) / 256), 256>>>(relh, rell);
    }
    // 3) weight transpose+split
    {
        dim3 b(32, 8);
        split_T<<<dim3(UU/32,  UU/32),  b>>>(Wq,   WqTh,   WqTl,   UU,  UU);
        split_T<<<dim3(2*UU/32,UU/32),  b>>>(Wkv,  WkvTh,  WkvTl,  UU,  2*UU);
        split_T<<<dim3(UU/32,  UU/32),  b>>>(Wr,   WrTh,   WrTl,   UU,  UU);
        split_T<<<dim3(UU/32,  UU/32),  b>>>(Wo,   WoTh,   WoTl,   UU,  UU);
        split_T<<<dim3(FFD/32, UU/32),  b>>>(W1,   W1Th,   W1Tl,   UU,  FFD);
        split_T<<<dim3(UU/32,  FFD/32), b>>>(W2,   W2Th,   W2Tl,   FFD, UU);
        split_T<<<dim3(NT/32,  UU/32),  b>>>(Wout, WoutTh, WoutTl, UU,  NT);
    }
    // 4) projections (HMMA)
    launch_hgemm(0, xh, xl, WqTh, WqTl, q, nullptr, nullptr, bq, M_TOK, UU, UU);
    launch_hgemm(0, fullh, fulll, WkvTh, WkvTl, kv, nullptr, nullptr, bkv, M_FULL, 2*UU, UU);
    launch_hgemm(0, relh, rell, WrTh, WrTl, r, nullptr, nullptr, br, KLEN, UU, UU);
    // 5) content + position scores (SIMT fp32)
    {
        dim3 grid((KLEN + 127) / 128, (SS + 127) / 128, BB * HH);
        sgemm2<128, true><<<grid, 256>>>(q, kv, ac, bias_c,
            SS, KLEN, DD, UU, 2*UU, KLEN, HH,
            (long long)SS*UU, 64,
            (long long)KLEN*2*UU, 64,
            (long long)HH*SS*KLEN, (long long)SS*KLEN, 64);
        sgemm2<128, true><<<grid, 256>>>(q, r, ar, bias_r,
            SS, KLEN, DD, UU, UU, KLEN, HH,
            (long long)SS*UU, 64,
            0, 64,
            (long long)HH*SS*KLEN, (long long)SS*KLEN, 64);
    }
    // 6) fused rel-shift + mask + softmax
    {
        dim3 grid(SS, BB * HH);
        attn_softmax<<<grid, 256>>>(ac, ar);
    }
    // 7) ctx = P @ V (SIMT)
    {
        dim3 grid(1, (SS + 127) / 128, BB * HH);
        sgemm2<64, false><<<grid, 256>>>(ac, kv + UU, ctx, nullptr,
            SS, DD, KLEN, KLEN, 2*UU, UU, HH,
            (long long)HH*SS*KLEN, (long long)SS*KLEN,
            (long long)KLEN*2*UU, 64,
            (long long)SS*UU, 64, 0);
    }
    // 8) split ctx, attention out projection, LN1
    {
        long long n = (long long)M_TOK * UU;
        split_rows<<<(unsigned)((n + 255) / 256), 256>>>(ctx, ctxh, ctxl, n);
    }
    launch_hgemm(0, ctxh, ctxl, WoTh, WoTl, tmp, nullptr, nullptr, bo, M_TOK, UU, UU);
    add_ln<<<M_TOK, 256>>>(x, tmp, ln1_g, ln1_b, h1, h1h, h1l);
    // 9) FF
    launch_hgemm(2, h1h, h1l, W1Th, W1Tl, nullptr, ffh, ffl, b1, M_TOK, FFD, UU);
    launch_hgemm(0, ffh, ffl, W2Th, W2Tl, tmp, nullptr, nullptr, b2, M_TOK, UU, FFD);
    add_ln<<<M_TOK, 256>>>(h1, tmp, ln2_g, ln2_b, h2, h2h, h2l);
    // 10) logits + softmax
    launch_hgemm(0, h2h, h2l, WoutTh, WoutTl, out, nullptr, nullptr, bout, M_TOK, NT, UU);
    softmax_rows<<<M_TOK, 512>>>(out, NT);
}

// round 5
// speedup vs baseline: 3.6080x; 1.2523x over previous
#include <cuda_runtime.h>
#include <cuda_bf16.h>
#include <math.h>
#include <stdint.h>

// ---------------- problem constants ----------------
#define BB 2
#define SS 1024
#define UU 1024
#define HH 16
#define DD 64
#define NT 32000
#define MEMLEN 576
#define FFD 4096
#define KLEN 1600   // MEM + S
#define VOCAB 1024

typedef __nv_bfloat16 bf16;

// ---------------- scratch (device globals; no allocation allowed) ----------------
__device__ float g_x   [(size_t)BB*SS*UU];
__device__ float g_q   [(size_t)BB*SS*UU];
__device__ float g_ac  [(size_t)BB*HH*SS*KLEN];
__device__ float g_ar  [(size_t)BB*HH*SS*KLEN];
__device__ float g_tmp [(size_t)BB*SS*UU];
__device__ float g_h1  [(size_t)BB*SS*UU];
__device__ float g_h2  [(size_t)BB*SS*UU];

// bf16 hi/lo split buffers
__device__ bf16 g_xh   [(size_t)BB*SS*UU],   g_xl   [(size_t)BB*SS*UU];
__device__ bf16 g_fullh[(size_t)BB*KLEN*UU], g_fulll[(size_t)BB*KLEN*UU];
__device__ bf16 g_relh [(size_t)KLEN*UU],    g_rell [(size_t)KLEN*UU];
__device__ bf16 g_qch  [(size_t)BB*SS*UU],   g_qcl  [(size_t)BB*SS*UU];
__device__ bf16 g_qrh  [(size_t)BB*SS*UU],   g_qrl  [(size_t)BB*SS*UU];
__device__ bf16 g_kvh  [(size_t)BB*KLEN*2*UU], g_kvl [(size_t)BB*KLEN*2*UU];
__device__ bf16 g_rh   [(size_t)KLEN*UU],    g_rl   [(size_t)KLEN*UU];
__device__ bf16 g_ph   [(size_t)BB*HH*SS*KLEN], g_pl [(size_t)BB*HH*SS*KLEN];
__device__ bf16 g_vth  [(size_t)BB*HH*DD*KLEN], g_vtl[(size_t)BB*HH*DD*KLEN];
__device__ bf16 g_ctxh [(size_t)BB*SS*UU],   g_ctxl [(size_t)BB*SS*UU];
__device__ bf16 g_h1h  [(size_t)BB*SS*UU],   g_h1l  [(size_t)BB*SS*UU];
__device__ bf16 g_h2h  [(size_t)BB*SS*UU],   g_h2l  [(size_t)BB*SS*UU];
__device__ bf16 g_ffh  [(size_t)BB*SS*FFD],  g_ffl  [(size_t)BB*SS*FFD];
// transposed weights [N,K] bf16 hi/lo
__device__ bf16 g_WqTh [(size_t)UU*UU],    g_WqTl [(size_t)UU*UU];
__device__ bf16 g_WkvTh[(size_t)2*UU*UU],  g_WkvTl[(size_t)2*UU*UU];
__device__ bf16 g_WrTh [(size_t)UU*UU],    g_WrTl [(size_t)UU*UU];
__device__ bf16 g_WoTh [(size_t)UU*UU],    g_WoTl [(size_t)UU*UU];
__device__ bf16 g_W1Th [(size_t)FFD*UU],   g_W1Tl [(size_t)FFD*UU];
__device__ bf16 g_W2Th [(size_t)UU*FFD],   g_W2Tl [(size_t)UU*FFD];
__device__ bf16 g_WoutTh[(size_t)NT*UU],   g_WoutTl[(size_t)NT*UU];

// ---------------- helpers ----------------
__device__ __forceinline__ uint32_t smem_u32(const void* p) {
    uint32_t a;
    asm("{ .reg .u64 t; cvta.to.shared.u64 t, %1; cvt.u32.u64 %0, t; }" : "=r"(a) : "l"(p));
    return a;
}
__device__ __forceinline__ void split_val(float v, bf16& h, bf16& l) {
    h = __float2bfloat16(v);
    l = __float2bfloat16(v - __bfloat162float(h));
}
__device__ __forceinline__ void cp16(uint32_t dst, const void* src) {
    asm volatile("cp.async.cg.shared.global [%0], [%1], 16;" :: "r"(dst), "l"(src));
}
__device__ __forceinline__ void ldx4(uint32_t* r, uint32_t addr) {
    asm volatile("ldmatrix.sync.aligned.m8n8.x4.shared.b16 {%0,%1,%2,%3}, [%4];"
                 : "=r"(r[0]), "=r"(r[1]), "=r"(r[2]), "=r"(r[3]) : "r"(addr));
}
__device__ __forceinline__ void ldx2(uint32_t* r, uint32_t addr) {
    asm volatile("ldmatrix.sync.aligned.m8n8.x2.shared.b16 {%0,%1}, [%2];"
                 : "=r"(r[0]), "=r"(r[1]) : "r"(addr));
}
__device__ __forceinline__ void mma16816(float* c, const uint32_t* a, const uint32_t* b) {
    asm volatile("mma.sync.aligned.m16n8k16.row.col.f32.bf16.bf16.f32 "
                 "{%0,%1,%2,%3}, {%4,%5,%6,%7}, {%8,%9}, {%0,%1,%2,%3};"
                 : "+f"(c[0]), "+f"(c[1]), "+f"(c[2]), "+f"(c[3])
                 : "r"(a[0]), "r"(a[1]), "r"(a[2]), "r"(a[3]), "r"(b[0]), "r"(b[1]));
}

// ---------------- generalized HMMA split-bf16 GEMM ----------------
// C[M,N](ldc) = (Ah+Al)[M,K](lda) @ (Bh+Bl)[N,K](ldb)^T + bias
// 3-pass split: hh + hl + lh, fp32 accum.
// Batch: z = blockIdx.z; z1 = z/Z2, z2 = z%Z2; base += z1*s?1 + z2*s?2.
// K % 16 == 0, K >= 64. M arbitrary (row clamp + store guard). N arbitrary
// (B-row clamp + store guard); bias (if non-null) requires N % BN == 0.
// OUT: 0 = fp32 C; 1 = split bf16 Ch/Cl; 2 = relu + split.
template<int BN, int OUT>
__global__ __launch_bounds__(256)
void hgemm(const bf16* __restrict__ Ah, const bf16* __restrict__ Al,
           const bf16* __restrict__ Bh, const bf16* __restrict__ Bl,
           float* __restrict__ C, bf16* __restrict__ Ch, bf16* __restrict__ Cl,
           const float* __restrict__ bias,
           int M, int N, int K, int lda, int ldb, int ldc, int Z2,
           long long sA1, long long sA2, long long sB1, long long sB2,
           long long sC1, long long sC2)
{
    constexpr int STAGE = 8192 + 2 * BN * 32;
    constexpr int MT = (BN == 128) ? 4 : 2;
    __shared__ __align__(128) char sm[3 * STAGE];
    const uint32_t smb = smem_u32(sm);
    const int tid = threadIdx.x, wid = tid >> 5, lane = tid & 31;
    const int m0 = blockIdx.y * 128, n0 = blockIdx.x * BN;
    const int m_w = (BN == 128) ? (wid & 1) * 64 : (wid & 3) * 32;
    const int n_w = (BN == 128) ? (wid >> 1) * 32 : (wid >> 2) * 32;

    const int z = blockIdx.z;
    const int z1 = z / Z2, z2 = z - z1 * Z2;
    Ah += z1 * sA1 + z2 * sA2;  Al += z1 * sA1 + z2 * sA2;
    Bh += z1 * sB1 + z2 * sB2;  Bl += z1 * sB1 + z2 * sB2;
    const long long cbase = z1 * sC1 + z2 * sC2;

    const int lr = tid >> 1, lc = tid & 1;
    const uint32_t so = (uint32_t)(lr * 32 + ((lc ^ ((lr >> 2) & 1)) << 4));
    const int ga = min(m0 + lr, M - 1);
    const long long aoff = (long long)ga * lda + lc * 8;
    const bool bdo = (BN == 128) || (tid < 128);
    const int gb = min(n0 + lr, N - 1);
    const long long boff = (long long)gb * ldb + lc * 8;

    float acc[MT][4][4];
    #pragma unroll
    for (int i = 0; i < MT; i++)
        #pragma unroll
        for (int j = 0; j < 4; j++)
            #pragma unroll
            for (int k = 0; k < 4; k++) acc[i][j][k] = 0.f;

    const int NC = K / 16;

    #pragma unroll
    for (int pc = 0; pc < 2; pc++) {
        const uint32_t st = smb + pc * STAGE;
        cp16(st + so,        Ah + aoff + pc * 16);
        cp16(st + 4096 + so, Al + aoff + pc * 16);
        if (bdo) {
            cp16(st + 8192 + so,           Bh + boff + pc * 16);
            cp16(st + 8192 + BN * 32 + so, Bl + boff + pc * 16);
        }
        asm volatile("cp.async.commit_group;");
    }

    const int rr = lane & 15, ccq = lane >> 4;
    const int rb = lane & 7,  cb = (lane >> 3) & 1;

    for (int c = 0; c < NC; c++) {
        if (c + 2 < NC) {
            const uint32_t st = smb + ((c + 2) % 3) * STAGE;
            const long long k0 = (long long)(c + 2) * 16;
            cp16(st + so,        Ah + aoff + k0);
            cp16(st + 4096 + so, Al + aoff + k0);
            if (bdo) {
                cp16(st + 8192 + so,           Bh + boff + k0);
                cp16(st + 8192 + BN * 32 + so, Bl + boff + k0);
            }
        }
        asm volatile("cp.async.commit_group;");
        asm volatile("cp.async.wait_group 2;");
        __syncthreads();

        const uint32_t st = smb + (c % 3) * STAGE;
        uint32_t ah[MT][4], al[MT][4], bh[4][2], bl[4][2];
        #pragma unroll
        for (int mt = 0; mt < MT; mt++) {
            int R = m_w + mt * 16 + rr;
            uint32_t ad = st + R * 32 + ((ccq ^ ((R >> 2) & 1)) << 4);
            ldx4(ah[mt], ad);
            ldx4(al[mt], ad + 4096);
        }
        #pragma unroll
        for (int nt = 0; nt < 4; nt++) {
            int Nr = n_w + nt * 8 + rb;
            uint32_t bd = st + 8192 + Nr * 32 + ((cb ^ ((Nr >> 2) & 1)) << 4);
            ldx2(bh[nt], bd);
            ldx2(bl[nt], bd + BN * 32);
        }
        #pragma unroll
        for (int mt = 0; mt < MT; mt++)
            #pragma unroll
            for (int nt = 0; nt < 4; nt++) {
                mma16816(acc[mt][nt], ah[mt], bh[nt]);
                mma16816(acc[mt][nt], ah[mt], bl[nt]);
                mma16816(acc[mt][nt], al[mt], bh[nt]);
            }
        __syncthreads();
    }

    // ---- epilogue ----
    #pragma unroll
    for (int mt = 0; mt < MT; mt++) {
        int gm0 = m0 + m_w + mt * 16 + (lane >> 2);
        #pragma unroll
        for (int nt = 0; nt < 4; nt++) {
            int gn = n0 + n_w + nt * 8 + (lane & 3) * 2;
            if (gn >= N) continue;
            float bx = 0.f, by = 0.f;
            if (bias) { float2 bv = *(const float2*)(bias + gn); bx = bv.x; by = bv.y; }
            float v0 = acc[mt][nt][0] + bx;
            float v1 = acc[mt][nt][1] + by;
            float v2 = acc[mt][nt][2] + bx;
            float v3 = acc[mt][nt][3] + by;
            if (OUT == 0) {
                if (gm0 < M) {
                    float2 w; w.x = v0; w.y = v1;
                    *(float2*)(C + cbase + (long long)gm0 * ldc + gn) = w;
                }
                if (gm0 + 8 < M) {
                    float2 w; w.x = v2; w.y = v3;
                    *(float2*)(C + cbase + (long long)(gm0 + 8) * ldc + gn) = w;
                }
            } else {
                if (OUT == 2) {
                    v0 = fmaxf(v0, 0.f); v1 = fmaxf(v1, 0.f);
                    v2 = fmaxf(v2, 0.f); v3 = fmaxf(v3, 0.f);
                }
                bf16 h0, l0, h1, l1;
                if (gm0 < M) {
                    long long o = cbase + (long long)gm0 * ldc + gn;
                    split_val(v0, h0, l0); split_val(v1, h1, l1);
                    __nv_bfloat162 ph; ph.x = h0; ph.y = h1;
                    __nv_bfloat162 pl; pl.x = l0; pl.y = l1;
                    *(__nv_bfloat162*)(Ch + o) = ph;
                    *(__nv_bfloat162*)(Cl + o) = pl;
                }
                if (gm0 + 8 < M) {
                    long long o = cbase + (long long)(gm0 + 8) * ldc + gn;
                    split_val(v2, h0, l0); split_val(v3, h1, l1);
                    __nv_bfloat162 ph; ph.x = h0; ph.y = h1;
                    __nv_bfloat162 pl; pl.x = l0; pl.y = l1;
                    *(__nv_bfloat162*)(Ch + o) = ph;
                    *(__nv_bfloat162*)(Cl + o) = pl;
                }
            }
        }
    }
}

// ---------------- reductions ----------------
__device__ __forceinline__ float block_reduce_sum(float v) {
    __shared__ float sm[16];
    __syncthreads();
    #pragma unroll
    for (int o = 16; o > 0; o >>= 1) v += __shfl_xor_sync(0xffffffffu, v, o);
    if ((threadIdx.x & 31) == 0) sm[threadIdx.x >> 5] = v;
    __syncthreads();
    if (threadIdx.x < 32) {
        float x = (threadIdx.x < (blockDim.x >> 5)) ? sm[threadIdx.x] : 0.f;
        #pragma unroll
        for (int o = 8; o > 0; o >>= 1) x += __shfl_xor_sync(0xffffffffu, x, o);
        if (threadIdx.x == 0) sm[0] = x;
    }
    __syncthreads();
    return sm[0];
}
__device__ __forceinline__ float block_reduce_max(float v) {
    __shared__ float sm[16];
    __syncthreads();
    #pragma unroll
    for (int o = 16; o > 0; o >>= 1) v = fmaxf(v, __shfl_xor_sync(0xffffffffu, v, o));
    if ((threadIdx.x & 31) == 0) sm[threadIdx.x >> 5] = v;
    __syncthreads();
    if (threadIdx.x < 32) {
        float x = (threadIdx.x < (blockDim.x >> 5)) ? sm[threadIdx.x] : -3.4e38f;
        #pragma unroll
        for (int o = 8; o > 0; o >>= 1) x = fmaxf(x, __shfl_xor_sync(0xffffffffu, x, o));
        if (threadIdx.x == 0) sm[0] = x;
    }
    __syncthreads();
    return sm[0];
}

// ---------------- small kernels ----------------
__global__ void build_full(const int* __restrict__ tokens,
                           const float* __restrict__ memory,
                           const float* __restrict__ embed,
                           float* __restrict__ x,
                           bf16* __restrict__ xh, bf16* __restrict__ xl,
                           bf16* __restrict__ fullh, bf16* __restrict__ fulll)
{
    long long idx = (long long)blockIdx.x * 256 + threadIdx.x;
    const long long tot = (long long)BB * KLEN * UU;
    if (idx >= tot) return;
    int u = (int)(idx % UU);
    long long t = idx / UU;
    int j = (int)(t % KLEN);
    int b = (int)(t / KLEN);
    float v;
    if (j < MEMLEN) {
        v = memory[((long long)b * MEMLEN + j) * UU + u];
    } else {
        int s = j - MEMLEN;
        int tok = tokens[b * SS + s];
        v = embed[(long long)tok * UU + u] * 32.0f;  // sqrt(1024)
        long long xo = ((long long)b * SS + s) * UU + u;
        x[xo] = v;
        bf16 h, l; split_val(v, h, l);
        xh[xo] = h; xl[xo] = l;
    }
    bf16 h, l; split_val(v, h, l);
    fullh[idx] = h; fulll[idx] = l;
}

__global__ void pos_embed(bf16* __restrict__ relh, bf16* __restrict__ rell)
{
    long long idx = (long long)blockIdx.x * 256 + threadIdx.x;
    if (idx >= (long long)KLEN * UU) return;
    int u = (int)(idx % UU);
    int jj = (int)(idx / UU);
    float pos = (float)(KLEN - 1 - jj);
    int i2 = (u < UU / 2) ? u : (u - UU / 2);
    float expo = ((float)(2 * i2)) / (float)UU;
    float invf = expf(-expo * 9.210340371976184f);  // ln(10000)
    float ang = pos * invf;
    float v = (u < UU / 2) ? sinf(ang) : cosf(ang);
    bf16 h, l; split_val(v, h, l);
    relh[idx] = h; rell[idx] = l;
}

// transpose + split: W[K,N] fp32 -> hi/lo[N,K] bf16 (K,N multiples of 32)
__global__ void split_T(const float* __restrict__ W, bf16* __restrict__ hi,
                        bf16* __restrict__ lo, int K, int N)
{
    __shared__ float t[32][33];
    int n0 = blockIdx.x * 32, k0 = blockIdx.y * 32;
    #pragma unroll
    for (int i = 0; i < 32; i += 8)
        t[threadIdx.y + i][threadIdx.x] =
            W[(long long)(k0 + threadIdx.y + i) * N + n0 + threadIdx.x];
    __syncthreads();
    #pragma unroll
    for (int i = 0; i < 32; i += 8) {
        float v = t[threadIdx.x][threadIdx.y + i];
        long long o = (long long)(n0 + threadIdx.y + i) * K + k0 + threadIdx.x;
        bf16 h, l; split_val(v, h, l);
        hi[o] = h; lo[o] = l;
    }
}

// q (fp32, incl bq) -> split(q+u), split(q+v)
__global__ void split_q(const float* __restrict__ q,
                        const float* __restrict__ uC, const float* __restrict__ uR,
                        bf16* __restrict__ qch, bf16* __restrict__ qcl,
                        bf16* __restrict__ qrh, bf16* __restrict__ qrl)
{
    long long idx = (long long)blockIdx.x * 256 + threadIdx.x;
    if (idx >= (long long)BB * SS * UU) return;
    int u = (int)(idx % UU);
    float v = q[idx];
    bf16 h, l;
    split_val(v + uC[u], h, l); qch[idx] = h; qcl[idx] = l;
    split_val(v + uR[u], h, l); qrh[idx] = h; qrl[idx] = l;
}

// V^T per head: vt[(b*H+h), d, j] = kv[b, j, U + h*64 + d]   (bf16 hi/lo)
__global__ void transpose_v(const bf16* __restrict__ kvh, const bf16* __restrict__ kvl,
                            bf16* __restrict__ vth, bf16* __restrict__ vtl)
{
    __shared__ bf16 th[32][33], tl[32][33];
    int z = blockIdx.z;           // b*H + h
    int b = z / HH, h = z % HH;
    int j0 = blockIdx.x * 32, d0 = blockIdx.y * 32;
    int tx = threadIdx.x, ty = threadIdx.y;
    #pragma unroll
    for (int i = 0; i < 32; i += 8) {
        long long src = ((long long)b * KLEN + j0 + ty + i) * (2 * UU) + UU + h * 64 + d0 + tx;
        th[ty + i][tx] = kvh[src];
        tl[ty + i][tx] = kvl[src];
    }
    __syncthreads();
    #pragma unroll
    for (int i = 0; i < 32; i += 8) {
        long long dst = ((long long)z * DD + d0 + ty + i) * KLEN + j0 + tx;
        vth[dst] = th[tx][ty + i];
        vtl[dst] = tl[tx][ty + i];
    }
}

// mask + rel-shift + softmax; writes P as split bf16 (zero tail)
__global__ __launch_bounds__(256)
void attn_softmax(const float* __restrict__ ac, const float* __restrict__ ar,
                  bf16* __restrict__ ph, bf16* __restrict__ pl)
{
    int i = blockIdx.x;
    long long z = blockIdx.y;
    const float* arow = ac + (z * SS + i) * (long long)KLEN;
    const float* rrow = ar + (z * SS + i) * (long long)KLEN;
    bf16* phr = ph + (z * SS + i) * (long long)KLEN;
    bf16* plr = pl + (z * SS + i) * (long long)KLEN;
    int lim = i + MEMLEN;
    int shift = SS - 1 - i;
    int tid = threadIdx.x;

    float vals[7];
    int cnt = 0;
    float lmax = -3.4e38f;
    for (int j = tid; j <= lim; j += 256) {
        float v = (arow[j] + rrow[j + shift]) * 0.125f;
        vals[cnt++] = v;
        lmax = fmaxf(lmax, v);
    }
    float m = block_reduce_max(lmax);
    float lsum = 0.f;
    for (int t = 0; t < cnt; t++) {
        float e = expf(vals[t] - m);
        vals[t] = e;
        lsum += e;
    }
    float s = block_reduce_sum(lsum);
    float inv = 1.f / s;
    cnt = 0;
    for (int j = tid; j <= lim; j += 256) {
        float p = vals[cnt++] * inv;
        bf16 h, l; split_val(p, h, l);
        phr[j] = h; plr[j] = l;
    }
    bf16 z0 = __float2bfloat16(0.f);
    for (int j = lim + 1 + tid; j < KLEN; j += 256) { phr[j] = z0; plr[j] = z0; }
}

__global__ __launch_bounds__(256)
void add_ln(const float* __restrict__ a, const float* __restrict__ b,
            const float* __restrict__ g, const float* __restrict__ beta,
            float* __restrict__ out, bf16* __restrict__ oh, bf16* __restrict__ ol)
{
    long long row = blockIdx.x;
    const float* pa = a + row * UU;
    const float* pb = b + row * UU;
    int tid = threadIdx.x;
    float vals[4];
    float s = 0.f, ss = 0.f;
    #pragma unroll
    for (int t = 0; t < 4; t++) {
        int idx = tid * 4 + t;
        float v = pa[idx] + pb[idx];
        vals[t] = v;
        s += v;
        ss += v * v;
    }
    s = block_reduce_sum(s);
    ss = block_reduce_sum(ss);
    float mean = s * (1.f / UU);
    float var = fmaxf(ss * (1.f / UU) - mean * mean, 0.f);
    float rstd = rsqrtf(var + 1e-5f);
    #pragma unroll
    for (int t = 0; t < 4; t++) {
        int idx = tid * 4 + t;
        float v = (vals[t] - mean) * rstd * g[idx] + beta[idx];
        out[row * UU + idx] = v;
        bf16 h, l; split_val(v, h, l);
        oh[row * UU + idx] = h; ol[row * UU + idx] = l;
    }
}

// online-softmax over vocab rows, in place (2 reads + 1 write)
__global__ __launch_bounds__(512)
void softmax_rows(float* __restrict__ x, int N)
{
    __shared__ float smm[16], sms[16];
    long long row = blockIdx.x;
    float* p = x + row * (long long)N;
    int tid = threadIdx.x;
    float m = -3.4e38f, s = 0.f;
    for (int j = tid; j < N; j += 512) {
        float v = p[j];
        if (v > m) { s = s * expf(m - v) + 1.f; m = v; }
        else       { s += expf(v - m); }
    }
    // merge across warp
    #pragma unroll
    for (int o = 16; o > 0; o >>= 1) {
        float m2 = __shfl_xor_sync(0xffffffffu, m, o);
        float s2 = __shfl_xor_sync(0xffffffffu, s, o);
        float M = fmaxf(m, m2);
        s = s * expf(m - M) + s2 * expf(m2 - M);
        m = M;
    }
    if ((tid & 31) == 0) { smm[tid >> 5] = m; sms[tid >> 5] = s; }
    __syncthreads();
    if (tid < 32) {
        float mm = (tid < 16) ? smm[tid] : -3.4e38f;
        float ssv = (tid < 16) ? sms[tid] : 0.f;
        #pragma unroll
        for (int o = 8; o > 0; o >>= 1) {
            float m2 = __shfl_xor_sync(0xffffffffu, mm, o);
            float s2 = __shfl_xor_sync(0xffffffffu, ssv, o);
            float M = fmaxf(mm, m2);
            ssv = ssv * expf(mm - M) + s2 * expf(m2 - M);
            mm = M;
        }
        if (tid == 0) { smm[0] = mm; sms[0] = ssv; }
    }
    __syncthreads();
    float M = smm[0];
    float inv = 1.f / sms[0];
    for (int j = tid; j < N; j += 512) p[j] = expf(p[j] - M) * inv;
}

// ---------------- host ----------------
extern "C" void kernel_launch(void* const* d_in, const int* in_sizes, int n_in,
                              void* d_out, int out_size)
{
    const int*   tokens  = (const int*)  d_in[0];
    const float* memory  = (const float*)d_in[1];
    const float* embed   = (const float*)d_in[2];
    const float* Wq      = (const float*)d_in[3];
    const float* Wkv     = (const float*)d_in[4];
    const float* Wr      = (const float*)d_in[5];
    const float* Wo      = (const float*)d_in[6];
    const float* bq      = (const float*)d_in[7];
    const float* bkv     = (const float*)d_in[8];
    const float* br      = (const float*)d_in[9];
    const float* bo      = (const float*)d_in[10];
    const float* bias_c  = (const float*)d_in[11];
    const float* bias_r  = (const float*)d_in[12];
    const float* ln1_g   = (const float*)d_in[13];
    const float* ln1_b   = (const float*)d_in[14];
    const float* W1      = (const float*)d_in[15];
    const float* b1      = (const float*)d_in[16];
    const float* W2      = (const float*)d_in[17];
    const float* b2      = (const float*)d_in[18];
    const float* ln2_g   = (const float*)d_in[19];
    const float* ln2_b   = (const float*)d_in[20];
    const float* Wout    = (const float*)d_in[21];
    const float* bout    = (const float*)d_in[22];
    float* out = (float*)d_out;

    float *x, *q, *ac, *ar, *tmp, *h1, *h2;
    cudaGetSymbolAddress((void**)&x,   g_x);
    cudaGetSymbolAddress((void**)&q,   g_q);
    cudaGetSymbolAddress((void**)&ac,  g_ac);
    cudaGetSymbolAddress((void**)&ar,  g_ar);
    cudaGetSymbolAddress((void**)&tmp, g_tmp);
    cudaGetSymbolAddress((void**)&h1,  g_h1);
    cudaGetSymbolAddress((void**)&h2,  g_h2);

    bf16 *xh,*xl,*fullh,*fulll,*relh,*rell;
    bf16 *qch,*qcl,*qrh,*qrl,*kvh,*kvl,*rh,*rl,*ph,*pl,*vth,*vtl;
    bf16 *ctxh,*ctxl,*h1h,*h1l,*h2h,*h2l,*ffh,*ffl;
    cudaGetSymbolAddress((void**)&xh, g_xh);       cudaGetSymbolAddress((void**)&xl, g_xl);
    cudaGetSymbolAddress((void**)&fullh, g_fullh); cudaGetSymbolAddress((void**)&fulll, g_fulll);
    cudaGetSymbolAddress((void**)&relh, g_relh);   cudaGetSymbolAddress((void**)&rell, g_rell);
    cudaGetSymbolAddress((void**)&qch, g_qch);     cudaGetSymbolAddress((void**)&qcl, g_qcl);
    cudaGetSymbolAddress((void**)&qrh, g_qrh);     cudaGetSymbolAddress((void**)&qrl, g_qrl);
    cudaGetSymbolAddress((void**)&kvh, g_kvh);     cudaGetSymbolAddress((void**)&kvl, g_kvl);
    cudaGetSymbolAddress((void**)&rh, g_rh);       cudaGetSymbolAddress((void**)&rl, g_rl);
    cudaGetSymbolAddress((void**)&ph, g_ph);       cudaGetSymbolAddress((void**)&pl, g_pl);
    cudaGetSymbolAddress((void**)&vth, g_vth);     cudaGetSymbolAddress((void**)&vtl, g_vtl);
    cudaGetSymbolAddress((void**)&ctxh, g_ctxh);   cudaGetSymbolAddress((void**)&ctxl, g_ctxl);
    cudaGetSymbolAddress((void**)&h1h, g_h1h);     cudaGetSymbolAddress((void**)&h1l, g_h1l);
    cudaGetSymbolAddress((void**)&h2h, g_h2h);     cudaGetSymbolAddress((void**)&h2l, g_h2l);
    cudaGetSymbolAddress((void**)&ffh, g_ffh);     cudaGetSymbolAddress((void**)&ffl, g_ffl);

    bf16 *WqTh,*WqTl,*WkvTh,*WkvTl,*WrTh,*WrTl,*WoTh,*WoTl,*W1Th,*W1Tl,*W2Th,*W2Tl,*WoutTh,*WoutTl;
    cudaGetSymbolAddress((void**)&WqTh, g_WqTh);   cudaGetSymbolAddress((void**)&WqTl, g_WqTl);
    cudaGetSymbolAddress((void**)&WkvTh, g_WkvTh); cudaGetSymbolAddress((void**)&WkvTl, g_WkvTl);
    cudaGetSymbolAddress((void**)&WrTh, g_WrTh);   cudaGetSymbolAddress((void**)&WrTl, g_WrTl);
    cudaGetSymbolAddress((void**)&WoTh, g_WoTh);   cudaGetSymbolAddress((void**)&WoTl, g_WoTl);
    cudaGetSymbolAddress((void**)&W1Th, g_W1Th);   cudaGetSymbolAddress((void**)&W1Tl, g_W1Tl);
    cudaGetSymbolAddress((void**)&W2Th, g_W2Th);   cudaGetSymbolAddress((void**)&W2Tl, g_W2Tl);
    cudaGetSymbolAddress((void**)&WoutTh, g_WoutTh); cudaGetSymbolAddress((void**)&WoutTl, g_WoutTl);

    const int M_TOK = BB * SS;      // 2048
    const int M_FULL = BB * KLEN;   // 3200

    // 1) embedding + concat + splits
    {
        long long tot = (long long)BB * KLEN * UU;
        build_full<<<(unsigned)((tot + 255) / 256), 256>>>(tokens, memory, embed,
                                                           x, xh, xl, fullh, fulll);
    }
    // 2) positional embedding
    {
        long long tot = (long long)KLEN * UU;
        pos_embed<<<(unsigned)((tot + 255) / 256), 256>>>(relh, rell);
    }
    // 3) weight transpose+split
    {
        dim3 b(32, 8);
        split_T<<<dim3(UU/32,  UU/32),  b>>>(Wq,   WqTh,   WqTl,   UU,  UU);
        split_T<<<dim3(2*UU/32,UU/32),  b>>>(Wkv,  WkvTh,  WkvTl,  UU,  2*UU);
        split_T<<<dim3(UU/32,  UU/32),  b>>>(Wr,   WrTh,   WrTl,   UU,  UU);
        split_T<<<dim3(UU/32,  UU/32),  b>>>(Wo,   WoTh,   WoTl,   UU,  UU);
        split_T<<<dim3(FFD/32, UU/32),  b>>>(W1,   W1Th,   W1Tl,   UU,  FFD);
        split_T<<<dim3(UU/32,  FFD/32), b>>>(W2,   W2Th,   W2Tl,   FFD, UU);
        split_T<<<dim3(NT/32,  UU/32),  b>>>(Wout, WoutTh, WoutTl, UU,  NT);
    }
    // 4) projections
    hgemm<128,0><<<dim3(UU/128, M_TOK/128, 1), 256>>>(
        xh, xl, WqTh, WqTl, q, nullptr, nullptr, bq,
        M_TOK, UU, UU, UU, UU, UU, 1, 0,0,0,0,0,0);
    hgemm<128,1><<<dim3(2*UU/128, (M_FULL+127)/128, 1), 256>>>(
        fullh, fulll, WkvTh, WkvTl, nullptr, kvh, kvl, bkv,
        M_FULL, 2*UU, UU, UU, UU, 2*UU, 1, 0,0,0,0,0,0);
    hgemm<128,1><<<dim3(UU/128, (KLEN+127)/128, 1), 256>>>(
        relh, rell, WrTh, WrTl, nullptr, rh, rl, br,
        KLEN, UU, UU, UU, UU, UU, 1, 0,0,0,0,0,0);
    // 5) q + biases -> splits
    {
        long long n = (long long)M_TOK * UU;
        split_q<<<(unsigned)((n + 255) / 256), 256>>>(q, bias_c, bias_r, qch, qcl, qrh, qrl);
    }
    // 6) scores (HMMA, batched over b,h)
    {
        dim3 grid((KLEN + 127) / 128, SS / 128, BB * HH);
        hgemm<128,0><<<grid, 256>>>(qch, qcl, kvh, kvl, ac, nullptr, nullptr, nullptr,
            SS, KLEN, DD, UU, 2*UU, KLEN, HH,
            (long long)SS*UU, 64,
            (long long)KLEN*2*UU, 64,
            (long long)HH*SS*KLEN, (long long)SS*KLEN);
        hgemm<128,0><<<grid, 256>>>(qrh, qrl, rh, rl, ar, nullptr, nullptr, nullptr,
            SS, KLEN, DD, UU, UU, KLEN, HH,
            (long long)SS*UU, 64,
            0, 64,
            (long long)HH*SS*KLEN, (long long)SS*KLEN);
    }
    // 7) fused rel-shift + mask + softmax -> split P
    {
        dim3 grid(SS, BB * HH);
        attn_softmax<<<grid, 256>>>(ac, ar, ph, pl);
    }
    // 8) V^T per head
    {
        dim3 grid(KLEN / 32, DD / 32, BB * HH);
        transpose_v<<<grid, dim3(32, 8)>>>(kvh, kvl, vth, vtl);
    }
    // 9) ctx = P @ V^T (HMMA, BN=64)
    {
        dim3 grid(1, SS / 128, BB * HH);
        hgemm<64,1><<<grid, 256>>>(ph, pl, vth, vtl, nullptr, ctxh, ctxl, nullptr,
            SS, DD, KLEN, KLEN, KLEN, UU, HH,
            (long long)HH*SS*KLEN, (long long)SS*KLEN,
            (long long)HH*DD*KLEN, (long long)DD*KLEN,
            (long long)SS*UU, 64);
    }
    // 10) attention out projection + LN1
    hgemm<128,0><<<dim3(UU/128, M_TOK/128, 1), 256>>>(
        ctxh, ctxl, WoTh, WoTl, tmp, nullptr, nullptr, bo,
        M_TOK, UU, UU, UU, UU, UU, 1, 0,0,0,0,0,0);
    add_ln<<<M_TOK, 256>>>(x, tmp, ln1_g, ln1_b, h1, h1h, h1l);
    // 11) FF
    hgemm<128,2><<<dim3(FFD/128, M_TOK/128, 1), 256>>>(
        h1h, h1l, W1Th, W1Tl, nullptr, ffh, ffl, b1,
        M_TOK, FFD, UU, UU, UU, FFD, 1, 0,0,0,0,0,0);
    hgemm<128,0><<<dim3(UU/128, M_TOK/128, 1), 256>>>(
        ffh, ffl, W2Th, W2Tl, tmp, nullptr, nullptr, b2,
        M_TOK, UU, FFD, FFD, FFD, UU, 1, 0,0,0,0,0,0);
    add_ln<<<M_TOK, 256>>>(h1, tmp, ln2_g, ln2_b, h2, h2h, h2l);
    // 12) logits + softmax
    hgemm<128,0><<<dim3(NT/128, M_TOK/128, 1), 256>>>(
        h2h, h2l, WoutTh, WoutTl, out, nullptr, nullptr, bout,
        M_TOK, NT, UU, UU, UU, NT, 1, 0,0,0,0,0,0);
    softmax_rows<<<M_TOK, 512>>>(out, NT);
}